// round 10
// baseline (speedup 1.0000x reference)
#include <cuda_runtime.h>
#include <cuda_fp16.h>
#include <float.h>
#include <math.h>

// Problem constants
#define NN   20000      // nodes
#define EE   320000     // edges (without self loops)
#define EPQ  340000     // edges + self loops
#define HHH  8          // GAT heads
#define GGG  64         // graphs
#define F1   256        // GAT out (H*32)
#define F2   512        // GCN1 out
#define F3   1024       // GCN2 / residual out
#define CAP  256        // smem edge cache per node

// ---------------------------------------------------------------------------
// Static scratch (no allocations allowed)
// ---------------------------------------------------------------------------
__device__ float g_h0  [NN * F1];     // x @ W_gat
__device__ float g_as  [NN * HHH];
__device__ float g_ad  [NN * HHH];
__device__ float g_res [NN * F3];     // residual branch
__device__ float g_t   [NN * F3];     // GEMM output before aggregation (reused)
__device__ float g_dinv[NN];
__device__ float g_wdeg[NN];
__device__ float g_pool[GGG * F3];
// CSR
__device__ int   g_cnt [NN];
__device__ int   g_off [NN + 1];
__device__ int   g_cur [NN];
__device__ int   g_csrc[EPQ];
__device__ float g_cw  [EPQ];
// fp16 2-term split GEMM operands:
//   A' = [A_hi | A_lo]  (M x 2K, K-major)   — exact split, fp32 accum
//   B' = [B_hi ; B_hi]  (2K x N, row-major) — dropped term A@B_lo ~ 2^-12
__device__ __half g_Ah[NN * 1024];      // max 2K = 1024
__device__ __half g_Bh[1024 * 1024];

// ---------------------------------------------------------------------------
// Helpers
// ---------------------------------------------------------------------------
__device__ __forceinline__ void atomicMaxFloat(float* addr, float val) {
    if (val >= 0.0f) atomicMax((int*)addr, __float_as_int(val));
    else             atomicMin((unsigned int*)addr, __float_as_uint(val));
}

__device__ __forceinline__ void ldsm4(unsigned& r0, unsigned& r1, unsigned& r2, unsigned& r3,
                                      unsigned a) {
    asm volatile("ldmatrix.sync.aligned.m8n8.x4.shared.b16 {%0,%1,%2,%3},[%4];"
                 : "=r"(r0), "=r"(r1), "=r"(r2), "=r"(r3) : "r"(a));
}
__device__ __forceinline__ void ldsm4t(unsigned& r0, unsigned& r1, unsigned& r2, unsigned& r3,
                                       unsigned a) {
    asm volatile("ldmatrix.sync.aligned.m8n8.x4.trans.shared.b16 {%0,%1,%2,%3},[%4];"
                 : "=r"(r0), "=r"(r1), "=r"(r2), "=r"(r3) : "r"(a));
}
__device__ __forceinline__ void mma16816(float* c, const unsigned* a, unsigned b0, unsigned b1) {
    asm volatile(
        "mma.sync.aligned.m16n8k16.row.col.f32.f16.f16.f32 "
        "{%0,%1,%2,%3}, {%4,%5,%6,%7}, {%8,%9}, {%0,%1,%2,%3};"
        : "+f"(c[0]), "+f"(c[1]), "+f"(c[2]), "+f"(c[3])
        : "r"(a[0]), "r"(a[1]), "r"(a[2]), "r"(a[3]), "r"(b0), "r"(b1));
}

// ---------------------------------------------------------------------------
// Init
// ---------------------------------------------------------------------------
__global__ void k_init() {
    int i = blockIdx.x * blockDim.x + threadIdx.x;
    int stride = gridDim.x * blockDim.x;
    for (int j = i; j < NN;       j += stride) { g_cnt[j] = 0; g_wdeg[j] = 0.0f; }
    for (int j = i; j < GGG * F3; j += stride) g_pool[j] = -FLT_MAX;
}

// ---------------------------------------------------------------------------
// CSR build
// ---------------------------------------------------------------------------
__global__ void k_count(const int* __restrict__ ei, const float* __restrict__ ew) {
    int e = blockIdx.x * blockDim.x + threadIdx.x;
    if (e >= EPQ) return;
    int dst; float w;
    if (e < EE) { dst = ei[EE + e]; w = ew[e]; }
    else        { dst = e - EE;     w = 1.0f; }
    atomicAdd(&g_cnt[dst], 1);
    atomicAdd(&g_wdeg[dst], w);
}

__global__ void k_scan() {   // 1 block, 1024 threads, warp-shuffle based
    __shared__ int wsum[32];
    __shared__ int carry;
    int tid = threadIdx.x, lane = tid & 31, w = tid >> 5;
    if (tid == 0) carry = 0;
    __syncthreads();
    for (int base = 0; base < NN; base += 1024) {
        int i = base + tid;
        int v = (i < NN) ? g_cnt[i] : 0;
        int x = v;
        #pragma unroll
        for (int o = 1; o < 32; o <<= 1) {
            int t = __shfl_up_sync(0xffffffffu, x, o);
            if (lane >= o) x += t;
        }
        if (lane == 31) wsum[w] = x;
        __syncthreads();
        if (w == 0) {
            int s = wsum[lane];
            #pragma unroll
            for (int o = 1; o < 32; o <<= 1) {
                int t = __shfl_up_sync(0xffffffffu, s, o);
                if (lane >= o) s += t;
            }
            wsum[lane] = s;
        }
        __syncthreads();
        int warpoff = (w == 0) ? 0 : wsum[w - 1];
        int excl = carry + warpoff + x - v;
        if (i < NN) { g_off[i] = excl; g_cur[i] = excl; }
        __syncthreads();
        if (tid == 0) carry += wsum[31];
        __syncthreads();
    }
    if (tid == 0) g_off[NN] = carry;
}

__global__ void k_dinv() {
    int n = blockIdx.x * blockDim.x + threadIdx.x;
    if (n >= NN) return;
    float d = g_wdeg[n];
    g_dinv[n] = (d > 0.f) ? rsqrtf(fmaxf(d, 1e-12f)) : 0.0f;
}

__global__ void k_fill(const int* __restrict__ ei, const float* __restrict__ ew) {
    int e = blockIdx.x * blockDim.x + threadIdx.x;
    if (e >= EPQ) return;
    int src, dst; float w;
    if (e < EE) { src = ei[e]; dst = ei[EE + e]; w = ew[e]; }
    else        { src = dst = e - EE; w = 1.0f; }
    int slot = atomicAdd(&g_cur[dst], 1);
    g_csrc[slot] = src;
    g_cw[slot]   = w;
}

// ---------------------------------------------------------------------------
// fp16 2-term split builders
// A' [M, 2K] = [hi | lo]  (exact: hi = fp16(x), lo = fp16(x - hi))
// ---------------------------------------------------------------------------
__global__ void k_splitA2(const float* __restrict__ src, __half* __restrict__ dst,
                          int M, int K) {
    int stride = gridDim.x * blockDim.x;
    int total = M * K;
    for (int i = blockIdx.x * blockDim.x + threadIdx.x; i < total; i += stride) {
        int row = i / K, k = i - row * K;
        float x = src[i];
        __half hi = __float2half(x);
        __half lo = __float2half(x - __half2float(hi));
        size_t rb = (size_t)row * 2 * K;
        dst[rb + k]     = hi;
        dst[rb + K + k] = lo;
    }
}
// B' [2K, N] = [hi ; hi]  (both blocks = fp16(B); dropped term is A @ B_lo)
__global__ void k_splitB2(const float* __restrict__ src, __half* __restrict__ dst,
                          int K, int N) {
    int stride = gridDim.x * blockDim.x;
    int total = K * N;
    for (int i = blockIdx.x * blockDim.x + threadIdx.x; i < total; i += stride) {
        int k = i / N, n = i - k * N;
        __half h = __float2half(src[i]);
        dst[(size_t)k * N + n]       = h;
        dst[(size_t)(K + k) * N + n] = h;
    }
}

// ---------------------------------------------------------------------------
// fp16 tensor-core GEMM: C[M,N] (fp32) = A'[M,Kp] @ B'[Kp,N] (+ bias[N])
// CTA tile 128x128, BK=32, 256 threads (8 warps, warp tile 32x64).
// mma.sync.m16n8k16 f16 -> f32, ldmatrix with conflict-free pitches.
// Requires N % 128 == 0, Kp % 32 == 0.
// ---------------------------------------------------------------------------
#define APITCH 40     // halves per A smem row (bank step 20 -> conflict free)
#define BPITCH 136    // halves per B smem row (bank step 4  -> conflict free)
#define ABUFB  (128 * APITCH * 2)
#define BBUFB  (32 * BPITCH * 2)

__global__ __launch_bounds__(256) void gemm_h16(
    const __half* __restrict__ Ab, const __half* __restrict__ Bb,
    float* __restrict__ C, const float* __restrict__ bias,
    int M, int N, int Kp)
{
    __shared__ __align__(16) __half As[2][128 * APITCH];
    __shared__ __align__(16) __half Bs[2][32 * BPITCH];

    int tid = threadIdx.x;
    int wid = tid >> 5, lane = tid & 31;
    int wm = (wid >> 1) * 32;
    int wn = (wid & 1) * 64;
    int g = lane >> 2, qp = lane & 3;
    int rowBase = blockIdx.y * 128;
    int colBase = blockIdx.x * 128;

    unsigned aBase = (unsigned)__cvta_generic_to_shared(&As[0][0]);
    unsigned bBase = (unsigned)__cvta_generic_to_shared(&Bs[0][0]);

    float cf[2][8][4];
    #pragma unroll
    for (int mf = 0; mf < 2; mf++)
        #pragma unroll
        for (int nf = 0; nf < 8; nf++)
            #pragma unroll
            for (int q = 0; q < 4; q++) cf[mf][nf][q] = 0.f;

    const uint4 zero4 = make_uint4(0u, 0u, 0u, 0u);
    int ar0 = tid >> 2,         akc0 = tid & 3;
    int ar1 = (tid + 256) >> 2, akc1 = tid & 3;
    int br0 = tid >> 4,         bnc0 = tid & 15;
    int br1 = (tid + 256) >> 4, bnc1 = tid & 15;

    uint4 pa0, pa1, pb0, pb1;
    {
        int r = rowBase + ar0;
        pa0 = (r < M) ? *(const uint4*)(Ab + (size_t)r * Kp + akc0 * 8) : zero4;
        r = rowBase + ar1;
        pa1 = (r < M) ? *(const uint4*)(Ab + (size_t)r * Kp + akc1 * 8) : zero4;
        pb0 = *(const uint4*)(Bb + (size_t)br0 * N + colBase + bnc0 * 8);
        pb1 = *(const uint4*)(Bb + (size_t)br1 * N + colBase + bnc1 * 8);
    }

    int KT = Kp >> 5;
    int buf = 0;
    *(uint4*)(&As[0][ar0 * APITCH + akc0 * 8]) = pa0;
    *(uint4*)(&As[0][ar1 * APITCH + akc1 * 8]) = pa1;
    *(uint4*)(&Bs[0][br0 * BPITCH + bnc0 * 8]) = pb0;
    *(uint4*)(&Bs[0][br1 * BPITCH + bnc1 * 8]) = pb1;
    __syncthreads();

    for (int kt = 0; kt < KT; kt++) {
        if (kt + 1 < KT) {
            int k0 = (kt + 1) << 5;
            int r = rowBase + ar0;
            pa0 = (r < M) ? *(const uint4*)(Ab + (size_t)r * Kp + k0 + akc0 * 8) : zero4;
            r = rowBase + ar1;
            pa1 = (r < M) ? *(const uint4*)(Ab + (size_t)r * Kp + k0 + akc1 * 8) : zero4;
            pb0 = *(const uint4*)(Bb + (size_t)(k0 + br0) * N + colBase + bnc0 * 8);
            pb1 = *(const uint4*)(Bb + (size_t)(k0 + br1) * N + colBase + bnc1 * 8);
        }
        unsigned aOff = aBase + buf * ABUFB;
        unsigned bOff = bBase + buf * BBUFB;
        #pragma unroll
        for (int ks = 0; ks < 32; ks += 16) {
            unsigned af[2][4];
            #pragma unroll
            for (int mf = 0; mf < 2; mf++) {
                unsigned addr = aOff +
                    (((wm + mf * 16 + (lane & 15)) * APITCH) + ks + ((lane >> 4) << 3)) * 2;
                ldsm4(af[mf][0], af[mf][1], af[mf][2], af[mf][3], addr);
            }
            #pragma unroll
            for (int p = 0; p < 4; p++) {
                unsigned bfr[4];
                unsigned addr = bOff +
                    (((ks + (lane & 15)) * BPITCH) + wn + p * 16 + ((lane >> 4) << 3)) * 2;
                ldsm4t(bfr[0], bfr[1], bfr[2], bfr[3], addr);
                #pragma unroll
                for (int mf = 0; mf < 2; mf++) {
                    mma16816(cf[mf][2 * p],     af[mf], bfr[0], bfr[1]);
                    mma16816(cf[mf][2 * p + 1], af[mf], bfr[2], bfr[3]);
                }
            }
        }
        if (kt + 1 < KT) {
            int nb = buf ^ 1;
            *(uint4*)(&As[nb][ar0 * APITCH + akc0 * 8]) = pa0;
            *(uint4*)(&As[nb][ar1 * APITCH + akc1 * 8]) = pa1;
            *(uint4*)(&Bs[nb][br0 * BPITCH + bnc0 * 8]) = pb0;
            *(uint4*)(&Bs[nb][br1 * BPITCH + bnc1 * 8]) = pb1;
            __syncthreads();
            buf = nb;
        }
    }

    #pragma unroll
    for (int mf = 0; mf < 2; mf++) {
        #pragma unroll
        for (int nf = 0; nf < 8; nf++) {
            int col = colBase + wn + nf * 8 + qp * 2;
            float b0 = 0.f, b1 = 0.f;
            if (bias) { b0 = bias[col]; b1 = bias[col + 1]; }
            int row0 = rowBase + wm + mf * 16 + g;
            if (row0 < M)
                *(float2*)(C + (size_t)row0 * N + col) =
                    make_float2(cf[mf][nf][0] + b0, cf[mf][nf][1] + b1);
            int row1 = row0 + 8;
            if (row1 < M)
                *(float2*)(C + (size_t)row1 * N + col) =
                    make_float2(cf[mf][nf][2] + b0, cf[mf][nf][3] + b1);
        }
    }
}

// ---------------------------------------------------------------------------
// Attention dot products
// ---------------------------------------------------------------------------
__global__ void k_attn_dots(const float* __restrict__ att_s,
                            const float* __restrict__ att_d)
{
    int idx = blockIdx.x * blockDim.x + threadIdx.x;
    if (idx >= NN * HHH) return;
    int n = idx >> 3, h = idx & 7;
    const float* hp = g_h0 + (size_t)n * F1 + h * 32;
    const float* sa = att_s + h * 32;
    const float* da = att_d + h * 32;
    float s = 0.f, d = 0.f;
    #pragma unroll
    for (int c = 0; c < 32; ++c) {
        float hv = hp[c];
        s = fmaf(hv, sa[c], s);
        d = fmaf(hv, da[c], d);
    }
    g_as[idx] = s;
    g_ad[idx] = d;
}

// ---------------------------------------------------------------------------
// Fused GAT: per-node softmax + feature gather + bias + relu.
// Writes h1 ONLY as its fp16 2-term split (h1 is consumed only by GEMMs):
//   g_Ah[n*512 + j] = hi, g_Ah[n*512 + 256 + j] = lo
// ---------------------------------------------------------------------------
__global__ __launch_bounds__(256) void k_gat_gather(const float* __restrict__ b_gat) {
    __shared__ float s_alpha[CAP * HHH];
    __shared__ int   s_src[CAP];
    __shared__ float s_ad[HHH];
    __shared__ float s_ms[HHH], s_si[HHH];

    int n = blockIdx.x;
    int start = g_off[n];
    int deg = g_off[n + 1] - start;
    int tid = threadIdx.x;
    int w = tid >> 5, l = tid & 31;

    if (tid < HHH) s_ad[tid] = g_ad[n * HHH + tid];
    int degc = deg < CAP ? deg : CAP;
    for (int i = tid; i < degc; i += 256) s_src[i] = g_csrc[start + i];
    __syncthreads();

    float m = -FLT_MAX, ssum = 0.f;
    float adh = s_ad[w];
    for (int i = l; i < deg; i += 32) {
        int src = (i < CAP) ? s_src[i] : g_csrc[start + i];
        float e = g_as[src * HHH + w] + adh;
        e = (e > 0.f) ? e : 0.2f * e;
        float mn = fmaxf(m, e);
        ssum = ssum * __expf(m - mn) + __expf(e - mn);
        m = mn;
        if (i < CAP) s_alpha[i * HHH + w] = e;
    }
    #pragma unroll
    for (int off = 16; off > 0; off >>= 1) {
        float m2 = __shfl_xor_sync(0xffffffffu, m, off);
        float s2 = __shfl_xor_sync(0xffffffffu, ssum, off);
        float mn = fmaxf(m, m2);
        ssum = ssum * __expf(m - mn) + s2 * __expf(m2 - mn);
        m = mn;
    }
    float inv = 1.0f / ssum;
    for (int i = l; i < degc; i += 32)
        s_alpha[i * HHH + w] = __expf(s_alpha[i * HHH + w] - m) * inv;
    if (l == 0) { s_ms[w] = m; s_si[w] = inv; }
    __syncthreads();

    int h = tid >> 5;
    float acc = 0.f;
    for (int i = 0; i < deg; i++) {
        int src; float alpha;
        if (i < CAP) { src = s_src[i]; alpha = s_alpha[i * HHH + h]; }
        else {
            src = g_csrc[start + i];
            float e = g_as[src * HHH + h] + s_ad[h];
            e = (e > 0.f) ? e : 0.2f * e;
            alpha = __expf(e - s_ms[h]) * s_si[h];
        }
        acc = fmaf(g_h0[(size_t)src * F1 + tid], alpha, acc);
    }
    float v = acc + b_gat[tid];
    v = v > 0.f ? v : 0.f;
    __half hi = __float2half(v);
    __half lo = __float2half(v - __half2float(hi));
    size_t rb = (size_t)n * (2 * F1);
    g_Ah[rb + tid]      = hi;
    g_Ah[rb + F1 + tid] = lo;
}

// ---------------------------------------------------------------------------
// GCN gather, F=512 (float2/thread), epilogue: +b2, BN1, relu.
// Writes a1 ONLY as fp16 split: g_Ah[n*1024 + j] / [n*1024 + 512 + j]
// ---------------------------------------------------------------------------
__global__ __launch_bounds__(256) void k_gcn_gather_f2(
    const float* __restrict__ t,
    const float* __restrict__ b2,
    const float* __restrict__ g1, const float* __restrict__ be1,
    const float* __restrict__ m1, const float* __restrict__ v1)
{
    __shared__ int   s_src[CAP];
    __shared__ float s_nrm[CAP];
    int n = blockIdx.x;
    int start = g_off[n];
    int deg = g_off[n + 1] - start;
    int tid = threadIdx.x;
    float dn = g_dinv[n];
    int degc = deg < CAP ? deg : CAP;
    for (int i = tid; i < degc; i += 256) {
        int s = g_csrc[start + i];
        s_src[i] = s;
        s_nrm[i] = g_dinv[s] * g_cw[start + i] * dn;
    }
    __syncthreads();

    float2 acc = make_float2(0.f, 0.f);
    for (int i = 0; i < deg; i++) {
        int src; float nrm;
        if (i < CAP) { src = s_src[i]; nrm = s_nrm[i]; }
        else {
            src = g_csrc[start + i];
            nrm = g_dinv[src] * g_cw[start + i] * dn;
        }
        float2 x = *(const float2*)(t + (size_t)src * F2 + tid * 2);
        acc.x = fmaf(x.x, nrm, acc.x);
        acc.y = fmaf(x.y, nrm, acc.y);
    }
    int j = tid * 2;
    float sc0 = g1[j]     * rsqrtf(v1[j]     + 1e-5f);
    float sc1 = g1[j + 1] * rsqrtf(v1[j + 1] + 1e-5f);
    float y0 = sc0 * (acc.x + b2[j]     - m1[j])     + be1[j];
    float y1 = sc1 * (acc.y + b2[j + 1] - m1[j + 1]) + be1[j + 1];
    y0 = y0 > 0.f ? y0 : 0.f;
    y1 = y1 > 0.f ? y1 : 0.f;
    __half h0 = __float2half(y0);
    __half h1 = __float2half(y1);
    __half l0 = __float2half(y0 - __half2float(h0));
    __half l1 = __float2half(y1 - __half2float(h1));
    size_t rb = (size_t)n * (2 * F2);
    *(__half2*)(g_Ah + rb + j)      = __halves2half2(h0, h1);
    *(__half2*)(g_Ah + rb + F2 + j) = __halves2half2(l0, l1);
}

// ---------------------------------------------------------------------------
// GCN gather, F=1024 (float4/thread), epilogue: +b3, BN2, relu, +res, max pool
// ---------------------------------------------------------------------------
__global__ __launch_bounds__(256) void k_gcn_gather_f3(
    const float* __restrict__ t,
    const float* __restrict__ b3,
    const float* __restrict__ g2, const float* __restrict__ be2,
    const float* __restrict__ m2, const float* __restrict__ v2,
    const int* __restrict__ batch)
{
    __shared__ int   s_src[CAP];
    __shared__ float s_nrm[CAP];
    int n = blockIdx.x;
    int start = g_off[n];
    int deg = g_off[n + 1] - start;
    int tid = threadIdx.x;
    float dn = g_dinv[n];
    int degc = deg < CAP ? deg : CAP;
    for (int i = tid; i < degc; i += 256) {
        int s = g_csrc[start + i];
        s_src[i] = s;
        s_nrm[i] = g_dinv[s] * g_cw[start + i] * dn;
    }
    __syncthreads();

    float4 acc = make_float4(0.f, 0.f, 0.f, 0.f);
    for (int i = 0; i < deg; i++) {
        int src; float nrm;
        if (i < CAP) { src = s_src[i]; nrm = s_nrm[i]; }
        else {
            src = g_csrc[start + i];
            nrm = g_dinv[src] * g_cw[start + i] * dn;
        }
        float4 x = *(const float4*)(t + (size_t)src * F3 + tid * 4);
        acc.x = fmaf(x.x, nrm, acc.x);
        acc.y = fmaf(x.y, nrm, acc.y);
        acc.z = fmaf(x.z, nrm, acc.z);
        acc.w = fmaf(x.w, nrm, acc.w);
    }
    int j = tid * 4;
    float4 rr = *(const float4*)(g_res + (size_t)n * F3 + j);
    float* pool = g_pool + (size_t)batch[n] * F3 + j;
    float a[4] = {acc.x, acc.y, acc.z, acc.w};
    float rs[4] = {rr.x, rr.y, rr.z, rr.w};
    #pragma unroll
    for (int c = 0; c < 4; c++) {
        float sc = g2[j + c] * rsqrtf(v2[j + c] + 1e-5f);
        float y = sc * (a[c] + b3[j + c] - m2[j + c]) + be2[j + c];
        y = (y > 0.f ? y : 0.f) + rs[c];
        atomicMaxFloat(pool + c, y);
    }
}

// ---------------------------------------------------------------------------
// MLP head
// ---------------------------------------------------------------------------
__global__ __launch_bounds__(256) void k_head(
    const float* __restrict__ Wf1, const float* __restrict__ bf1,
    const float* __restrict__ Wf2, const float* __restrict__ bf2,
    float* __restrict__ out)
{
    __shared__ float sp[F3];
    __shared__ float sr0[256];
    __shared__ float sr1[256];
    int gb = blockIdx.x, tid = threadIdx.x;
    for (int i = tid; i < F3; i += 256) sp[i] = g_pool[(size_t)gb * F3 + i];
    __syncthreads();

    float acc = bf1[tid];
    #pragma unroll 4
    for (int k = 0; k < F3; ++k)
        acc = fmaf(sp[k], Wf1[(size_t)k * 256 + tid], acc);
    acc = acc > 0.f ? acc : 0.f;

    sr0[tid] = acc * Wf2[tid * 2 + 0];
    sr1[tid] = acc * Wf2[tid * 2 + 1];
    __syncthreads();
    for (int s = 128; s > 0; s >>= 1) {
        if (tid < s) { sr0[tid] += sr0[tid + s]; sr1[tid] += sr1[tid + s]; }
        __syncthreads();
    }
    if (tid == 0) {
        out[gb * 2 + 0] = sr0[0] + bf2[0];
        out[gb * 2 + 1] = sr1[0] + bf2[1];
    }
}

// ---------------------------------------------------------------------------
// Launch
// ---------------------------------------------------------------------------
extern "C" void kernel_launch(void* const* d_in, const int* in_sizes, int n_in,
                              void* d_out, int out_size)
{
    const float* x       = (const float*)d_in[0];
    const int*   ei      = (const int*)  d_in[1];
    const float* ew      = (const float*)d_in[2];
    const int*   batch   = (const int*)  d_in[3];
    const float* W_gat   = (const float*)d_in[4];
    const float* att_src = (const float*)d_in[5];
    const float* att_dst = (const float*)d_in[6];
    const float* b_gat   = (const float*)d_in[7];
    const float* W_res   = (const float*)d_in[8];
    const float* b_res   = (const float*)d_in[9];
    const float* W2      = (const float*)d_in[10];
    const float* b2      = (const float*)d_in[11];
    const float* g1      = (const float*)d_in[12];
    const float* be1     = (const float*)d_in[13];
    const float* m1      = (const float*)d_in[14];
    const float* v1      = (const float*)d_in[15];
    const float* W3      = (const float*)d_in[16];
    const float* b3      = (const float*)d_in[17];
    const float* g2      = (const float*)d_in[18];
    const float* be2     = (const float*)d_in[19];
    const float* m2      = (const float*)d_in[20];
    const float* v2      = (const float*)d_in[21];
    const float* Wf1     = (const float*)d_in[22];
    const float* bf1     = (const float*)d_in[23];
    const float* Wf2     = (const float*)d_in[24];
    const float* bf2     = (const float*)d_in[25];
    float* out = (float*)d_out;

    float *p_h0, *p_res, *p_t;
    __half *p_Ah, *p_Bh;
    cudaGetSymbolAddress((void**)&p_h0,  g_h0);
    cudaGetSymbolAddress((void**)&p_res, g_res);
    cudaGetSymbolAddress((void**)&p_t,   g_t);
    cudaGetSymbolAddress((void**)&p_Ah,  g_Ah);
    cudaGetSymbolAddress((void**)&p_Bh,  g_Bh);

    const int rowTiles = (NN + 127) / 128;  // 157
    const int egrid = (EPQ + 255) / 256;

    // CSR build
    k_init<<<512, 256>>>();
    k_count<<<egrid, 256>>>(ei, ew);
    k_scan<<<1, 1024>>>();
    k_dinv<<<(NN + 255) / 256, 256>>>();
    k_fill<<<egrid, 256>>>(ei, ew);

    // GAT: h0 = x @ W_gat   [20000,32]x[32,256]  (fp16 2-term, Kp=64)
    k_splitA2<<<2048, 256>>>(x, p_Ah, NN, 32);
    k_splitB2<<<32, 256>>>(W_gat, p_Bh, 32, F1);
    gemm_h16<<<dim3(F1 / 128, rowTiles), 256>>>(p_Ah, p_Bh, p_h0, nullptr, NN, F1, 64);
    k_attn_dots<<<(NN * HHH + 255) / 256, 256>>>(att_src, att_dst);
    k_gat_gather<<<NN, 256>>>(b_gat);   // writes h1 split into g_Ah [NN, 512]

    // residual + GCN1 GEMMs share the h1 split (Kp=512)
    k_splitB2<<<1024, 256>>>(W_res, p_Bh, F1, F3);
    gemm_h16<<<dim3(F3 / 128, rowTiles), 256>>>(p_Ah, p_Bh, p_res, b_res, NN, F3, 512);
    k_splitB2<<<512, 256>>>(W2, p_Bh, F1, F2);
    gemm_h16<<<dim3(F2 / 128, rowTiles), 256>>>(p_Ah, p_Bh, p_t, nullptr, NN, F2, 512);
    k_gcn_gather_f2<<<NN, 256>>>(p_t, b2, g1, be1, m1, v1);  // writes a1 split [NN,1024]

    // GCN2: t = a1 @ W3 (Kp=1024); gather+BN2+relu+res+pool
    k_splitB2<<<2048, 256>>>(W3, p_Bh, F2, F3);
    gemm_h16<<<dim3(F3 / 128, rowTiles), 256>>>(p_Ah, p_Bh, p_t, nullptr, NN, F3, 1024);
    k_gcn_gather_f3<<<NN, 256>>>(p_t, b3, g2, be2, m2, v2, batch);

    // MLP head
    k_head<<<GGG, 256>>>(Wf1, bf1, Wf2, bf2, out);
}

// round 11
// speedup vs baseline: 1.2677x; 1.2677x over previous
#include <cuda_runtime.h>
#include <cuda_bf16.h>
#include <float.h>
#include <math.h>

// Problem constants
#define NN   20000      // nodes
#define EE   320000     // edges (without self loops)
#define EPQ  340000     // edges + self loops
#define HHH  8          // GAT heads
#define GGG  64         // graphs
#define F1   256        // GAT out (H*32)
#define F2   512        // GCN1 out
#define F3   1024       // GCN2 / residual out
#define CAP  256        // smem edge cache per node

// ---------------------------------------------------------------------------
// Static scratch (no allocations allowed)
// ---------------------------------------------------------------------------
__device__ float g_h0  [NN * F1];     // x @ W_gat
__device__ float g_as  [NN * HHH];
__device__ float g_ad  [NN * HHH];
__device__ float g_res [NN * F3];     // residual branch
__device__ float g_t   [NN * F3];     // GEMM output before aggregation (reused)
__device__ float g_dinv[NN];
__device__ float g_wdeg[NN];
__device__ float g_pool[GGG * F3];
// CSR
__device__ int   g_cnt [NN];
__device__ int   g_off [NN + 1];
__device__ int   g_cur [NN];
__device__ int   g_csrc[EPQ];
__device__ float g_cw  [EPQ];
// split-bf16 3-term GEMM operands:
//   A' = [A_hi | A_lo | A_hi]  (M x 3K, K-major)
//   B' = [B_hi ; B_hi ; B_lo]  (3K x N, row-major)
// A@B ~ A_hi@B_hi + A_lo@B_hi + A_hi@B_lo  (dropped A_lo@B_lo ~ 2^-18 rel)
__device__ __nv_bfloat16 g_Ab[NN * 1536];      // max 3K = 1536
__device__ __nv_bfloat16 g_Bb[1536 * 1024];

// ---------------------------------------------------------------------------
// Helpers
// ---------------------------------------------------------------------------
__device__ __forceinline__ void atomicMaxFloat(float* addr, float val) {
    if (val >= 0.0f) atomicMax((int*)addr, __float_as_int(val));
    else             atomicMin((unsigned int*)addr, __float_as_uint(val));
}

__device__ __forceinline__ void ldsm4(unsigned& r0, unsigned& r1, unsigned& r2, unsigned& r3,
                                      unsigned a) {
    asm volatile("ldmatrix.sync.aligned.m8n8.x4.shared.b16 {%0,%1,%2,%3},[%4];"
                 : "=r"(r0), "=r"(r1), "=r"(r2), "=r"(r3) : "r"(a));
}
__device__ __forceinline__ void ldsm4t(unsigned& r0, unsigned& r1, unsigned& r2, unsigned& r3,
                                       unsigned a) {
    asm volatile("ldmatrix.sync.aligned.m8n8.x4.trans.shared.b16 {%0,%1,%2,%3},[%4];"
                 : "=r"(r0), "=r"(r1), "=r"(r2), "=r"(r3) : "r"(a));
}
__device__ __forceinline__ void mma16816(float* c, const unsigned* a, unsigned b0, unsigned b1) {
    asm volatile(
        "mma.sync.aligned.m16n8k16.row.col.f32.bf16.bf16.f32 "
        "{%0,%1,%2,%3}, {%4,%5,%6,%7}, {%8,%9}, {%0,%1,%2,%3};"
        : "+f"(c[0]), "+f"(c[1]), "+f"(c[2]), "+f"(c[3])
        : "r"(a[0]), "r"(a[1]), "r"(a[2]), "r"(a[3]), "r"(b0), "r"(b1));
}

__device__ __forceinline__ __nv_bfloat162 bsplit_hi2(float a, float b,
                                                     __nv_bfloat162& lo2) {
    __nv_bfloat16 h0 = __float2bfloat16(a);
    __nv_bfloat16 h1 = __float2bfloat16(b);
    __nv_bfloat16 l0 = __float2bfloat16(a - __bfloat162float(h0));
    __nv_bfloat16 l1 = __float2bfloat16(b - __bfloat162float(h1));
    __nv_bfloat162 hi2; hi2.x = h0; hi2.y = h1;
    lo2.x = l0; lo2.y = l1;
    return hi2;
}

// ---------------------------------------------------------------------------
// Init
// ---------------------------------------------------------------------------
__global__ void k_init() {
    int i = blockIdx.x * blockDim.x + threadIdx.x;
    int stride = gridDim.x * blockDim.x;
    for (int j = i; j < NN;       j += stride) { g_cnt[j] = 0; g_wdeg[j] = 0.0f; }
    for (int j = i; j < GGG * F3; j += stride) g_pool[j] = -FLT_MAX;
}

// ---------------------------------------------------------------------------
// CSR build
// ---------------------------------------------------------------------------
__global__ void k_count(const int* __restrict__ ei, const float* __restrict__ ew) {
    int e = blockIdx.x * blockDim.x + threadIdx.x;
    if (e >= EPQ) return;
    int dst; float w;
    if (e < EE) { dst = ei[EE + e]; w = ew[e]; }
    else        { dst = e - EE;     w = 1.0f; }
    atomicAdd(&g_cnt[dst], 1);
    atomicAdd(&g_wdeg[dst], w);
}

// 1 block, 1024 threads: exclusive-scan counts (warp-shuffle) + dinv
__global__ void k_scan() {
    __shared__ int wsum[32];
    __shared__ int carry;
    int tid = threadIdx.x, lane = tid & 31, w = tid >> 5;
    if (tid == 0) carry = 0;
    __syncthreads();
    for (int base = 0; base < NN; base += 1024) {
        int i = base + tid;
        int v = (i < NN) ? g_cnt[i] : 0;
        int x = v;
        #pragma unroll
        for (int o = 1; o < 32; o <<= 1) {
            int t = __shfl_up_sync(0xffffffffu, x, o);
            if (lane >= o) x += t;
        }
        if (lane == 31) wsum[w] = x;
        __syncthreads();
        if (w == 0) {
            int s = wsum[lane];
            #pragma unroll
            for (int o = 1; o < 32; o <<= 1) {
                int t = __shfl_up_sync(0xffffffffu, s, o);
                if (lane >= o) s += t;
            }
            wsum[lane] = s;
        }
        __syncthreads();
        int warpoff = (w == 0) ? 0 : wsum[w - 1];
        int excl = carry + warpoff + x - v;
        if (i < NN) {
            g_off[i] = excl;
            g_cur[i] = excl;
            float d = g_wdeg[i];
            g_dinv[i] = (d > 0.f) ? rsqrtf(fmaxf(d, 1e-12f)) : 0.0f;
        }
        __syncthreads();
        if (tid == 0) carry += wsum[31];
        __syncthreads();
    }
    if (tid == 0) g_off[NN] = carry;
}

__global__ void k_fill(const int* __restrict__ ei, const float* __restrict__ ew) {
    int e = blockIdx.x * blockDim.x + threadIdx.x;
    if (e >= EPQ) return;
    int src, dst; float w;
    if (e < EE) { src = ei[e]; dst = ei[EE + e]; w = ew[e]; }
    else        { src = dst = e - EE; w = 1.0f; }
    int slot = atomicAdd(&g_cur[dst], 1);
    g_csrc[slot] = src;
    g_cw[slot]   = w;
}

// ---------------------------------------------------------------------------
// Split fp32 -> bf16 hi/lo operand builders
// A' [M, 3K] = [hi | lo | hi]
// ---------------------------------------------------------------------------
__global__ void k_splitA(const float* __restrict__ src, __nv_bfloat16* __restrict__ dst,
                         int M, int K) {
    int stride = gridDim.x * blockDim.x;
    int total = M * K;
    for (int i = blockIdx.x * blockDim.x + threadIdx.x; i < total; i += stride) {
        int row = i / K, k = i - row * K;
        float x = src[i];
        __nv_bfloat16 hi = __float2bfloat16(x);
        __nv_bfloat16 lo = __float2bfloat16(x - __bfloat162float(hi));
        size_t rb = (size_t)row * 3 * K;
        dst[rb + k]         = hi;
        dst[rb + K + k]     = lo;
        dst[rb + 2 * K + k] = hi;
    }
}
// B' [3K, N] = [hi ; hi ; lo]
__global__ void k_splitB(const float* __restrict__ src, __nv_bfloat16* __restrict__ dst,
                         int K, int N) {
    int stride = gridDim.x * blockDim.x;
    int total = K * N;
    for (int i = blockIdx.x * blockDim.x + threadIdx.x; i < total; i += stride) {
        int k = i / N, n = i - k * N;
        float x = src[i];
        __nv_bfloat16 hi = __float2bfloat16(x);
        __nv_bfloat16 lo = __float2bfloat16(x - __bfloat162float(hi));
        dst[(size_t)k * N + n]           = hi;
        dst[(size_t)(K + k) * N + n]     = hi;
        dst[(size_t)(2 * K + k) * N + n] = lo;
    }
}

// ---------------------------------------------------------------------------
// bf16 tensor-core GEMM: C[M,N] (fp32) = A'[M,Kp] @ B'[Kp,N] (+ bias[N])
// CTA tile 128x128, BK=32, 256 threads (8 warps, warp tile 32x64).
// mma.sync.m16n8k16 bf16 -> f32, ldmatrix with conflict-free pitches.
// Requires N % 128 == 0, Kp % 32 == 0.   (verified at 1211us / rel_err 7.8e-6)
// ---------------------------------------------------------------------------
#define APITCH 40     // bf16 elems per A smem row (bank step 20 -> conflict free)
#define BPITCH 136    // bf16 elems per B smem row (bank step 4  -> conflict free)
#define ABUFB  (128 * APITCH * 2)
#define BBUFB  (32 * BPITCH * 2)

__global__ __launch_bounds__(256) void gemm_bf16s(
    const __nv_bfloat16* __restrict__ Ab, const __nv_bfloat16* __restrict__ Bb,
    float* __restrict__ C, const float* __restrict__ bias,
    int M, int N, int Kp)
{
    __shared__ __align__(16) __nv_bfloat16 As[2][128 * APITCH];
    __shared__ __align__(16) __nv_bfloat16 Bs[2][32 * BPITCH];

    int tid = threadIdx.x;
    int wid = tid >> 5, lane = tid & 31;
    int wm = (wid >> 1) * 32;
    int wn = (wid & 1) * 64;
    int g = lane >> 2, qp = lane & 3;
    int rowBase = blockIdx.y * 128;
    int colBase = blockIdx.x * 128;

    unsigned aBase = (unsigned)__cvta_generic_to_shared(&As[0][0]);
    unsigned bBase = (unsigned)__cvta_generic_to_shared(&Bs[0][0]);

    float cf[2][8][4];
    #pragma unroll
    for (int mf = 0; mf < 2; mf++)
        #pragma unroll
        for (int nf = 0; nf < 8; nf++)
            #pragma unroll
            for (int q = 0; q < 4; q++) cf[mf][nf][q] = 0.f;

    const uint4 zero4 = make_uint4(0u, 0u, 0u, 0u);
    int ar0 = tid >> 2,         akc0 = tid & 3;
    int ar1 = (tid + 256) >> 2, akc1 = tid & 3;
    int br0 = tid >> 4,         bnc0 = tid & 15;
    int br1 = (tid + 256) >> 4, bnc1 = tid & 15;

    uint4 pa0, pa1, pb0, pb1;
    {
        int r = rowBase + ar0;
        pa0 = (r < M) ? *(const uint4*)(Ab + (size_t)r * Kp + akc0 * 8) : zero4;
        r = rowBase + ar1;
        pa1 = (r < M) ? *(const uint4*)(Ab + (size_t)r * Kp + akc1 * 8) : zero4;
        pb0 = *(const uint4*)(Bb + (size_t)br0 * N + colBase + bnc0 * 8);
        pb1 = *(const uint4*)(Bb + (size_t)br1 * N + colBase + bnc1 * 8);
    }

    int KT = Kp >> 5;
    int buf = 0;
    *(uint4*)(&As[0][ar0 * APITCH + akc0 * 8]) = pa0;
    *(uint4*)(&As[0][ar1 * APITCH + akc1 * 8]) = pa1;
    *(uint4*)(&Bs[0][br0 * BPITCH + bnc0 * 8]) = pb0;
    *(uint4*)(&Bs[0][br1 * BPITCH + bnc1 * 8]) = pb1;
    __syncthreads();

    for (int kt = 0; kt < KT; kt++) {
        if (kt + 1 < KT) {
            int k0 = (kt + 1) << 5;
            int r = rowBase + ar0;
            pa0 = (r < M) ? *(const uint4*)(Ab + (size_t)r * Kp + k0 + akc0 * 8) : zero4;
            r = rowBase + ar1;
            pa1 = (r < M) ? *(const uint4*)(Ab + (size_t)r * Kp + k0 + akc1 * 8) : zero4;
            pb0 = *(const uint4*)(Bb + (size_t)(k0 + br0) * N + colBase + bnc0 * 8);
            pb1 = *(const uint4*)(Bb + (size_t)(k0 + br1) * N + colBase + bnc1 * 8);
        }
        unsigned aOff = aBase + buf * ABUFB;
        unsigned bOff = bBase + buf * BBUFB;
        #pragma unroll
        for (int ks = 0; ks < 32; ks += 16) {
            unsigned af[2][4];
            #pragma unroll
            for (int mf = 0; mf < 2; mf++) {
                unsigned addr = aOff +
                    (((wm + mf * 16 + (lane & 15)) * APITCH) + ks + ((lane >> 4) << 3)) * 2;
                ldsm4(af[mf][0], af[mf][1], af[mf][2], af[mf][3], addr);
            }
            #pragma unroll
            for (int p = 0; p < 4; p++) {
                unsigned bfr[4];
                unsigned addr = bOff +
                    (((ks + (lane & 15)) * BPITCH) + wn + p * 16 + ((lane >> 4) << 3)) * 2;
                ldsm4t(bfr[0], bfr[1], bfr[2], bfr[3], addr);
                #pragma unroll
                for (int mf = 0; mf < 2; mf++) {
                    mma16816(cf[mf][2 * p],     af[mf], bfr[0], bfr[1]);
                    mma16816(cf[mf][2 * p + 1], af[mf], bfr[2], bfr[3]);
                }
            }
        }
        if (kt + 1 < KT) {
            int nb = buf ^ 1;
            *(uint4*)(&As[nb][ar0 * APITCH + akc0 * 8]) = pa0;
            *(uint4*)(&As[nb][ar1 * APITCH + akc1 * 8]) = pa1;
            *(uint4*)(&Bs[nb][br0 * BPITCH + bnc0 * 8]) = pb0;
            *(uint4*)(&Bs[nb][br1 * BPITCH + bnc1 * 8]) = pb1;
            __syncthreads();
            buf = nb;
        }
    }

    #pragma unroll
    for (int mf = 0; mf < 2; mf++) {
        #pragma unroll
        for (int nf = 0; nf < 8; nf++) {
            int col = colBase + wn + nf * 8 + qp * 2;
            float b0 = 0.f, b1 = 0.f;
            if (bias) { b0 = bias[col]; b1 = bias[col + 1]; }
            int row0 = rowBase + wm + mf * 16 + g;
            if (row0 < M)
                *(float2*)(C + (size_t)row0 * N + col) =
                    make_float2(cf[mf][nf][0] + b0, cf[mf][nf][1] + b1);
            int row1 = row0 + 8;
            if (row1 < M)
                *(float2*)(C + (size_t)row1 * N + col) =
                    make_float2(cf[mf][nf][2] + b0, cf[mf][nf][3] + b1);
        }
    }
}

// ---------------------------------------------------------------------------
// Attention dot products
// ---------------------------------------------------------------------------
__global__ void k_attn_dots(const float* __restrict__ att_s,
                            const float* __restrict__ att_d)
{
    int idx = blockIdx.x * blockDim.x + threadIdx.x;
    if (idx >= NN * HHH) return;
    int n = idx >> 3, h = idx & 7;
    const float* hp = g_h0 + (size_t)n * F1 + h * 32;
    const float* sa = att_s + h * 32;
    const float* da = att_d + h * 32;
    float s = 0.f, d = 0.f;
    #pragma unroll
    for (int c = 0; c < 32; ++c) {
        float hv = hp[c];
        s = fmaf(hv, sa[c], s);
        d = fmaf(hv, da[c], d);
    }
    g_as[idx] = s;
    g_ad[idx] = d;
}

// ---------------------------------------------------------------------------
// Fused GAT: per-node softmax + feature gather + bias + relu.
// Writes h1 directly as its bf16 3-term split into g_Ab:
//   row base n*768: [0:256)=hi, [256:512)=lo, [512:768)=hi
// ---------------------------------------------------------------------------
__global__ __launch_bounds__(256) void k_gat_gather(const float* __restrict__ b_gat) {
    __shared__ float s_alpha[CAP * HHH];
    __shared__ int   s_src[CAP];
    __shared__ float s_ad[HHH];
    __shared__ float s_ms[HHH], s_si[HHH];

    int n = blockIdx.x;
    int start = g_off[n];
    int deg = g_off[n + 1] - start;
    int tid = threadIdx.x;
    int w = tid >> 5, l = tid & 31;

    if (tid < HHH) s_ad[tid] = g_ad[n * HHH + tid];
    int degc = deg < CAP ? deg : CAP;
    for (int i = tid; i < degc; i += 256) s_src[i] = g_csrc[start + i];
    __syncthreads();

    float m = -FLT_MAX, ssum = 0.f;
    float adh = s_ad[w];
    for (int i = l; i < deg; i += 32) {
        int src = (i < CAP) ? s_src[i] : g_csrc[start + i];
        float e = g_as[src * HHH + w] + adh;
        e = (e > 0.f) ? e : 0.2f * e;
        float mn = fmaxf(m, e);
        ssum = ssum * __expf(m - mn) + __expf(e - mn);
        m = mn;
        if (i < CAP) s_alpha[i * HHH + w] = e;
    }
    #pragma unroll
    for (int off = 16; off > 0; off >>= 1) {
        float m2 = __shfl_xor_sync(0xffffffffu, m, off);
        float s2 = __shfl_xor_sync(0xffffffffu, ssum, off);
        float mn = fmaxf(m, m2);
        ssum = ssum * __expf(m - mn) + s2 * __expf(m2 - mn);
        m = mn;
    }
    float inv = 1.0f / ssum;
    for (int i = l; i < degc; i += 32)
        s_alpha[i * HHH + w] = __expf(s_alpha[i * HHH + w] - m) * inv;
    if (l == 0) { s_ms[w] = m; s_si[w] = inv; }
    __syncthreads();

    int h = tid >> 5;
    float acc = 0.f;
    for (int i = 0; i < deg; i++) {
        int src; float alpha;
        if (i < CAP) { src = s_src[i]; alpha = s_alpha[i * HHH + h]; }
        else {
            src = g_csrc[start + i];
            float e = g_as[src * HHH + h] + s_ad[h];
            e = (e > 0.f) ? e : 0.2f * e;
            alpha = __expf(e - s_ms[h]) * s_si[h];
        }
        acc = fmaf(g_h0[(size_t)src * F1 + tid], alpha, acc);
    }
    float v = acc + b_gat[tid];
    v = v > 0.f ? v : 0.f;
    __nv_bfloat16 hi = __float2bfloat16(v);
    __nv_bfloat16 lo = __float2bfloat16(v - __bfloat162float(hi));
    size_t rb = (size_t)n * (3 * F1);
    g_Ab[rb + tid]            = hi;
    g_Ab[rb + F1 + tid]       = lo;
    g_Ab[rb + 2 * F1 + tid]   = hi;
}

// ---------------------------------------------------------------------------
// GCN gather, F=512 (float2/thread), epilogue: +b2, BN1, relu.
// Writes a1 directly as bf16 3-term split: row base n*1536.
// ---------------------------------------------------------------------------
__global__ __launch_bounds__(256) void k_gcn_gather_f2(
    const float* __restrict__ t,
    const float* __restrict__ b2,
    const float* __restrict__ g1, const float* __restrict__ be1,
    const float* __restrict__ m1, const float* __restrict__ v1)
{
    __shared__ int   s_src[CAP];
    __shared__ float s_nrm[CAP];
    int n = blockIdx.x;
    int start = g_off[n];
    int deg = g_off[n + 1] - start;
    int tid = threadIdx.x;
    float dn = g_dinv[n];
    int degc = deg < CAP ? deg : CAP;
    for (int i = tid; i < degc; i += 256) {
        int s = g_csrc[start + i];
        s_src[i] = s;
        s_nrm[i] = g_dinv[s] * g_cw[start + i] * dn;
    }
    __syncthreads();

    float2 acc = make_float2(0.f, 0.f);
    for (int i = 0; i < deg; i++) {
        int src; float nrm;
        if (i < CAP) { src = s_src[i]; nrm = s_nrm[i]; }
        else {
            src = g_csrc[start + i];
            nrm = g_dinv[src] * g_cw[start + i] * dn;
        }
        float2 x = *(const float2*)(t + (size_t)src * F2 + tid * 2);
        acc.x = fmaf(x.x, nrm, acc.x);
        acc.y = fmaf(x.y, nrm, acc.y);
    }
    int j = tid * 2;
    float sc0 = g1[j]     * rsqrtf(v1[j]     + 1e-5f);
    float sc1 = g1[j + 1] * rsqrtf(v1[j + 1] + 1e-5f);
    float y0 = sc0 * (acc.x + b2[j]     - m1[j])     + be1[j];
    float y1 = sc1 * (acc.y + b2[j + 1] - m1[j + 1]) + be1[j + 1];
    y0 = y0 > 0.f ? y0 : 0.f;
    y1 = y1 > 0.f ? y1 : 0.f;
    __nv_bfloat162 lo2;
    __nv_bfloat162 hi2 = bsplit_hi2(y0, y1, lo2);
    size_t rb = (size_t)n * (3 * F2);
    *(__nv_bfloat162*)(g_Ab + rb + j)            = hi2;
    *(__nv_bfloat162*)(g_Ab + rb + F2 + j)       = lo2;
    *(__nv_bfloat162*)(g_Ab + rb + 2 * F2 + j)   = hi2;
}

// ---------------------------------------------------------------------------
// GCN gather, F=1024 (float4/thread), epilogue: +b3, BN2, relu, +res, max pool
// ---------------------------------------------------------------------------
__global__ __launch_bounds__(256) void k_gcn_gather_f3(
    const float* __restrict__ t,
    const float* __restrict__ b3,
    const float* __restrict__ g2, const float* __restrict__ be2,
    const float* __restrict__ m2, const float* __restrict__ v2,
    const int* __restrict__ batch)
{
    __shared__ int   s_src[CAP];
    __shared__ float s_nrm[CAP];
    int n = blockIdx.x;
    int start = g_off[n];
    int deg = g_off[n + 1] - start;
    int tid = threadIdx.x;
    float dn = g_dinv[n];
    int degc = deg < CAP ? deg : CAP;
    for (int i = tid; i < degc; i += 256) {
        int s = g_csrc[start + i];
        s_src[i] = s;
        s_nrm[i] = g_dinv[s] * g_cw[start + i] * dn;
    }
    __syncthreads();

    float4 acc = make_float4(0.f, 0.f, 0.f, 0.f);
    for (int i = 0; i < deg; i++) {
        int src; float nrm;
        if (i < CAP) { src = s_src[i]; nrm = s_nrm[i]; }
        else {
            src = g_csrc[start + i];
            nrm = g_dinv[src] * g_cw[start + i] * dn;
        }
        float4 x = *(const float4*)(t + (size_t)src * F3 + tid * 4);
        acc.x = fmaf(x.x, nrm, acc.x);
        acc.y = fmaf(x.y, nrm, acc.y);
        acc.z = fmaf(x.z, nrm, acc.z);
        acc.w = fmaf(x.w, nrm, acc.w);
    }
    int j = tid * 4;
    float4 rr = *(const float4*)(g_res + (size_t)n * F3 + j);
    float* pool = g_pool + (size_t)batch[n] * F3 + j;
    float a[4] = {acc.x, acc.y, acc.z, acc.w};
    float rs[4] = {rr.x, rr.y, rr.z, rr.w};
    #pragma unroll
    for (int c = 0; c < 4; c++) {
        float sc = g2[j + c] * rsqrtf(v2[j + c] + 1e-5f);
        float y = sc * (a[c] + b3[j + c] - m2[j + c]) + be2[j + c];
        y = (y > 0.f ? y : 0.f) + rs[c];
        atomicMaxFloat(pool + c, y);
    }
}

// ---------------------------------------------------------------------------
// MLP head
// ---------------------------------------------------------------------------
__global__ __launch_bounds__(256) void k_head(
    const float* __restrict__ Wf1, const float* __restrict__ bf1,
    const float* __restrict__ Wf2, const float* __restrict__ bf2,
    float* __restrict__ out)
{
    __shared__ float sp[F3];
    __shared__ float sr0[256];
    __shared__ float sr1[256];
    int gb = blockIdx.x, tid = threadIdx.x;
    for (int i = tid; i < F3; i += 256) sp[i] = g_pool[(size_t)gb * F3 + i];
    __syncthreads();

    float acc = bf1[tid];
    #pragma unroll 4
    for (int k = 0; k < F3; ++k)
        acc = fmaf(sp[k], Wf1[(size_t)k * 256 + tid], acc);
    acc = acc > 0.f ? acc : 0.f;

    sr0[tid] = acc * Wf2[tid * 2 + 0];
    sr1[tid] = acc * Wf2[tid * 2 + 1];
    __syncthreads();
    for (int s = 128; s > 0; s >>= 1) {
        if (tid < s) { sr0[tid] += sr0[tid + s]; sr1[tid] += sr1[tid + s]; }
        __syncthreads();
    }
    if (tid == 0) {
        out[gb * 2 + 0] = sr0[0] + bf2[0];
        out[gb * 2 + 1] = sr1[0] + bf2[1];
    }
}

// ---------------------------------------------------------------------------
// Launch
// ---------------------------------------------------------------------------
extern "C" void kernel_launch(void* const* d_in, const int* in_sizes, int n_in,
                              void* d_out, int out_size)
{
    const float* x       = (const float*)d_in[0];
    const int*   ei      = (const int*)  d_in[1];
    const float* ew      = (const float*)d_in[2];
    const int*   batch   = (const int*)  d_in[3];
    const float* W_gat   = (const float*)d_in[4];
    const float* att_src = (const float*)d_in[5];
    const float* att_dst = (const float*)d_in[6];
    const float* b_gat   = (const float*)d_in[7];
    const float* W_res   = (const float*)d_in[8];
    const float* b_res   = (const float*)d_in[9];
    const float* W2      = (const float*)d_in[10];
    const float* b2      = (const float*)d_in[11];
    const float* g1      = (const float*)d_in[12];
    const float* be1     = (const float*)d_in[13];
    const float* m1      = (const float*)d_in[14];
    const float* v1      = (const float*)d_in[15];
    const float* W3      = (const float*)d_in[16];
    const float* b3      = (const float*)d_in[17];
    const float* g2      = (const float*)d_in[18];
    const float* be2     = (const float*)d_in[19];
    const float* m2      = (const float*)d_in[20];
    const float* v2      = (const float*)d_in[21];
    const float* Wf1     = (const float*)d_in[22];
    const float* bf1     = (const float*)d_in[23];
    const float* Wf2     = (const float*)d_in[24];
    const float* bf2     = (const float*)d_in[25];
    float* out = (float*)d_out;

    float *p_h0, *p_res, *p_t;
    __nv_bfloat16 *p_Ab, *p_Bb;
    cudaGetSymbolAddress((void**)&p_h0,  g_h0);
    cudaGetSymbolAddress((void**)&p_res, g_res);
    cudaGetSymbolAddress((void**)&p_t,   g_t);
    cudaGetSymbolAddress((void**)&p_Ab,  g_Ab);
    cudaGetSymbolAddress((void**)&p_Bb,  g_Bb);

    const int rowTiles = (NN + 127) / 128;  // 157
    const int egrid = (EPQ + 255) / 256;

    // CSR build
    k_init<<<512, 256>>>();
    k_count<<<egrid, 256>>>(ei, ew);
    k_scan<<<1, 1024>>>();          // offsets + dinv
    k_fill<<<egrid, 256>>>(ei, ew);

    // GAT: h0 = x @ W_gat   [20000,32]x[32,256]  (bf16 3-term, Kp=96)
    k_splitA<<<2048, 256>>>(x, p_Ab, NN, 32);
    k_splitB<<<64, 256>>>(W_gat, p_Bb, 32, F1);
    gemm_bf16s<<<dim3(F1 / 128, rowTiles), 256>>>(p_Ab, p_Bb, p_h0, nullptr, NN, F1, 96);
    k_attn_dots<<<(NN * HHH + 255) / 256, 256>>>(att_src, att_dst);
    k_gat_gather<<<NN, 256>>>(b_gat);   // writes h1 split into g_Ab [NN, 768]

    // residual + GCN1 share the h1 split (Kp=768)
    k_splitB<<<1024, 256>>>(W_res, p_Bb, F1, F3);
    gemm_bf16s<<<dim3(F3 / 128, rowTiles), 256>>>(p_Ab, p_Bb, p_res, b_res, NN, F3, 768);
    k_splitB<<<512, 256>>>(W2, p_Bb, F1, F2);
    gemm_bf16s<<<dim3(F2 / 128, rowTiles), 256>>>(p_Ab, p_Bb, p_t, nullptr, NN, F2, 768);
    k_gcn_gather_f2<<<NN, 256>>>(p_t, b2, g1, be1, m1, v1);  // writes a1 split [NN,1536]

    // GCN2: t = a1 @ W3 (Kp=1536); gather+BN2+relu+res+pool
    k_splitB<<<2048, 256>>>(W3, p_Bb, F2, F3);
    gemm_bf16s<<<dim3(F3 / 128, rowTiles), 256>>>(p_Ab, p_Bb, p_t, nullptr, NN, F3, 1536);
    k_gcn_gather_f3<<<NN, 256>>>(p_t, b3, g2, be2, m2, v2, batch);

    // MLP head
    k_head<<<GGG, 256>>>(Wf1, bf1, Wf2, bf2, out);
}

// round 13
// speedup vs baseline: 1.5024x; 1.1852x over previous
#include <cuda_runtime.h>
#include <cuda_bf16.h>
#include <float.h>
#include <math.h>

// Problem constants
#define NN   20000      // nodes
#define EE   320000     // edges (without self loops)
#define EPQ  340000     // edges + self loops
#define HHH  8          // GAT heads
#define GGG  64         // graphs
#define F1   256        // GAT out (H*32)
#define F2   512        // GCN1 out
#define F3   1024       // GCN2 / residual out
#define CAP  256        // smem edge cache per node

// ---------------------------------------------------------------------------
// Static scratch (no allocations allowed)
// ---------------------------------------------------------------------------
__device__ float g_h0  [NN * F1];     // x @ W_gat
__device__ float g_as  [NN * HHH];
__device__ float g_ad  [NN * HHH];
__device__ float g_h1f [NN * F1];     // GAT output fp32 (for aggregation)
__device__ float g_a1f [NN * F2];     // GCN1 output fp32 (for aggregation)
__device__ float g_res [NN * F3];     // residual branch
__device__ float g_dinv[NN];
__device__ float g_wdeg[NN];
__device__ float g_pool[GGG * F3];
// CSR
__device__ int   g_cnt [NN];
__device__ int   g_off [NN + 1];
__device__ int   g_cur [NN];
__device__ int   g_csrc[EPQ];
__device__ float g_cw  [EPQ];
// split-bf16 3-term GEMM operands:
//   A' = [A_hi | A_lo | A_hi]  (M x 3K, K-major)
//   B' = [B_hi ; B_hi ; B_lo]  (3K x N, row-major)
// A@B ~ A_hi@B_hi + A_lo@B_hi + A_hi@B_lo  (dropped A_lo@B_lo ~ 2^-18 rel)
__device__ __nv_bfloat16 g_Ab[NN * 1536];      // max 3K = 1536
__device__ __nv_bfloat16 g_Bb[1536 * 1024];

// ---------------------------------------------------------------------------
// Helpers
// ---------------------------------------------------------------------------
__device__ __forceinline__ void atomicMaxFloat(float* addr, float val) {
    if (val >= 0.0f) atomicMax((int*)addr, __float_as_int(val));
    else             atomicMin((unsigned int*)addr, __float_as_uint(val));
}

__device__ __forceinline__ void ldsm4(unsigned& r0, unsigned& r1, unsigned& r2, unsigned& r3,
                                      unsigned a) {
    asm volatile("ldmatrix.sync.aligned.m8n8.x4.shared.b16 {%0,%1,%2,%3},[%4];"
                 : "=r"(r0), "=r"(r1), "=r"(r2), "=r"(r3) : "r"(a));
}
__device__ __forceinline__ void ldsm4t(unsigned& r0, unsigned& r1, unsigned& r2, unsigned& r3,
                                       unsigned a) {
    asm volatile("ldmatrix.sync.aligned.m8n8.x4.trans.shared.b16 {%0,%1,%2,%3},[%4];"
                 : "=r"(r0), "=r"(r1), "=r"(r2), "=r"(r3) : "r"(a));
}
__device__ __forceinline__ void mma16816(float* c, const unsigned* a, unsigned b0, unsigned b1) {
    asm volatile(
        "mma.sync.aligned.m16n8k16.row.col.f32.bf16.bf16.f32 "
        "{%0,%1,%2,%3}, {%4,%5,%6,%7}, {%8,%9}, {%0,%1,%2,%3};"
        : "+f"(c[0]), "+f"(c[1]), "+f"(c[2]), "+f"(c[3])
        : "r"(a[0]), "r"(a[1]), "r"(a[2]), "r"(a[3]), "r"(b0), "r"(b1));
}

__device__ __forceinline__ __nv_bfloat162 bsplit_hi2(float a, float b,
                                                     __nv_bfloat162& lo2) {
    __nv_bfloat16 h0 = __float2bfloat16(a);
    __nv_bfloat16 h1 = __float2bfloat16(b);
    __nv_bfloat16 l0 = __float2bfloat16(a - __bfloat162float(h0));
    __nv_bfloat16 l1 = __float2bfloat16(b - __bfloat162float(h1));
    __nv_bfloat162 hi2; hi2.x = h0; hi2.y = h1;
    lo2.x = l0; lo2.y = l1;
    return hi2;
}

// ---------------------------------------------------------------------------
// Init
// ---------------------------------------------------------------------------
__global__ void k_init() {
    int i = blockIdx.x * blockDim.x + threadIdx.x;
    int stride = gridDim.x * blockDim.x;
    for (int j = i; j < NN;       j += stride) { g_cnt[j] = 0; g_wdeg[j] = 0.0f; }
    for (int j = i; j < GGG * F3; j += stride) g_pool[j] = -FLT_MAX;
}

// ---------------------------------------------------------------------------
// CSR build
// ---------------------------------------------------------------------------
__global__ void k_count(const int* __restrict__ ei, const float* __restrict__ ew) {
    int e = blockIdx.x * blockDim.x + threadIdx.x;
    if (e >= EPQ) return;
    int dst; float w;
    if (e < EE) { dst = ei[EE + e]; w = ew[e]; }
    else        { dst = e - EE;     w = 1.0f; }
    atomicAdd(&g_cnt[dst], 1);
    atomicAdd(&g_wdeg[dst], w);
}

// 1 block, 1024 threads: exclusive-scan counts (warp-shuffle) + dinv
__global__ void k_scan() {
    __shared__ int wsum[32];
    __shared__ int carry;
    int tid = threadIdx.x, lane = tid & 31, w = tid >> 5;
    if (tid == 0) carry = 0;
    __syncthreads();
    for (int base = 0; base < NN; base += 1024) {
        int i = base + tid;
        int v = (i < NN) ? g_cnt[i] : 0;
        int x = v;
        #pragma unroll
        for (int o = 1; o < 32; o <<= 1) {
            int t = __shfl_up_sync(0xffffffffu, x, o);
            if (lane >= o) x += t;
        }
        if (lane == 31) wsum[w] = x;
        __syncthreads();
        if (w == 0) {
            int s = wsum[lane];
            #pragma unroll
            for (int o = 1; o < 32; o <<= 1) {
                int t = __shfl_up_sync(0xffffffffu, s, o);
                if (lane >= o) s += t;
            }
            wsum[lane] = s;
        }
        __syncthreads();
        int warpoff = (w == 0) ? 0 : wsum[w - 1];
        int excl = carry + warpoff + x - v;
        if (i < NN) {
            g_off[i] = excl;
            g_cur[i] = excl;
            float d = g_wdeg[i];
            g_dinv[i] = (d > 0.f) ? rsqrtf(fmaxf(d, 1e-12f)) : 0.0f;
        }
        __syncthreads();
        if (tid == 0) carry += wsum[31];
        __syncthreads();
    }
    if (tid == 0) g_off[NN] = carry;
}

__global__ void k_fill(const int* __restrict__ ei, const float* __restrict__ ew) {
    int e = blockIdx.x * blockDim.x + threadIdx.x;
    if (e >= EPQ) return;
    int src, dst; float w;
    if (e < EE) { src = ei[e]; dst = ei[EE + e]; w = ew[e]; }
    else        { src = dst = e - EE; w = 1.0f; }
    int slot = atomicAdd(&g_cur[dst], 1);
    g_csrc[slot] = src;
    g_cw[slot]   = w;
}

// ---------------------------------------------------------------------------
// Split fp32 -> bf16 hi/lo operand builders
// ---------------------------------------------------------------------------
__global__ void k_splitA(const float* __restrict__ src, __nv_bfloat16* __restrict__ dst,
                         int M, int K) {
    int stride = gridDim.x * blockDim.x;
    int total = M * K;
    for (int i = blockIdx.x * blockDim.x + threadIdx.x; i < total; i += stride) {
        int row = i / K, k = i - row * K;
        float x = src[i];
        __nv_bfloat16 hi = __float2bfloat16(x);
        __nv_bfloat16 lo = __float2bfloat16(x - __bfloat162float(hi));
        size_t rb = (size_t)row * 3 * K;
        dst[rb + k]         = hi;
        dst[rb + K + k]     = lo;
        dst[rb + 2 * K + k] = hi;
    }
}
__global__ void k_splitB(const float* __restrict__ src, __nv_bfloat16* __restrict__ dst,
                         int K, int N) {
    int stride = gridDim.x * blockDim.x;
    int total = K * N;
    for (int i = blockIdx.x * blockDim.x + threadIdx.x; i < total; i += stride) {
        int k = i / N, n = i - k * N;
        float x = src[i];
        __nv_bfloat16 hi = __float2bfloat16(x);
        __nv_bfloat16 lo = __float2bfloat16(x - __bfloat162float(hi));
        dst[(size_t)k * N + n]           = hi;
        dst[(size_t)(K + k) * N + n]     = hi;
        dst[(size_t)(2 * K + k) * N + n] = lo;
    }
}

// ---------------------------------------------------------------------------
// bf16 tensor-core GEMM, templated epilogue:
//  MODE 0: C = v (+bias)
//  MODE 1: C = relu(BN(v+bias))              (fp32 out)
//  MODE 2: y = relu(BN(v+bias)) + res; atomicMax(pool[batch[row]*N+col], y)
// CTA tile 128x128, BK=32, 256 threads (8 warps, warp tile 32x64).
// ---------------------------------------------------------------------------
#define APITCH 40
#define BPITCH 136
#define ABUFB  (128 * APITCH * 2)
#define BBUFB  (32 * BPITCH * 2)

template<int MODE>
__global__ __launch_bounds__(256) void gemm_k(
    const __nv_bfloat16* __restrict__ Ab, const __nv_bfloat16* __restrict__ Bb,
    float* __restrict__ C, const float* __restrict__ bias,
    const float* __restrict__ bg, const float* __restrict__ bbe,
    const float* __restrict__ bm, const float* __restrict__ bv,
    const float* __restrict__ res, const int* __restrict__ batch,
    float* __restrict__ pool,
    int M, int N, int Kp)
{
    __shared__ __align__(16) __nv_bfloat16 As[2][128 * APITCH];
    __shared__ __align__(16) __nv_bfloat16 Bs[2][32 * BPITCH];

    int tid = threadIdx.x;
    int wid = tid >> 5, lane = tid & 31;
    int wm = (wid >> 1) * 32;
    int wn = (wid & 1) * 64;
    int g = lane >> 2, qp = lane & 3;
    int rowBase = blockIdx.y * 128;
    int colBase = blockIdx.x * 128;

    unsigned aBase = (unsigned)__cvta_generic_to_shared(&As[0][0]);
    unsigned bBase = (unsigned)__cvta_generic_to_shared(&Bs[0][0]);

    float cf[2][8][4];
    #pragma unroll
    for (int mf = 0; mf < 2; mf++)
        #pragma unroll
        for (int nf = 0; nf < 8; nf++)
            #pragma unroll
            for (int q = 0; q < 4; q++) cf[mf][nf][q] = 0.f;

    const uint4 zero4 = make_uint4(0u, 0u, 0u, 0u);
    int ar0 = tid >> 2,         akc0 = tid & 3;
    int ar1 = (tid + 256) >> 2, akc1 = tid & 3;
    int br0 = tid >> 4,         bnc0 = tid & 15;
    int br1 = (tid + 256) >> 4, bnc1 = tid & 15;

    uint4 pa0, pa1, pb0, pb1;
    {
        int r = rowBase + ar0;
        pa0 = (r < M) ? *(const uint4*)(Ab + (size_t)r * Kp + akc0 * 8) : zero4;
        r = rowBase + ar1;
        pa1 = (r < M) ? *(const uint4*)(Ab + (size_t)r * Kp + akc1 * 8) : zero4;
        pb0 = *(const uint4*)(Bb + (size_t)br0 * N + colBase + bnc0 * 8);
        pb1 = *(const uint4*)(Bb + (size_t)br1 * N + colBase + bnc1 * 8);
    }

    int KT = Kp >> 5;
    int buf = 0;
    *(uint4*)(&As[0][ar0 * APITCH + akc0 * 8]) = pa0;
    *(uint4*)(&As[0][ar1 * APITCH + akc1 * 8]) = pa1;
    *(uint4*)(&Bs[0][br0 * BPITCH + bnc0 * 8]) = pb0;
    *(uint4*)(&Bs[0][br1 * BPITCH + bnc1 * 8]) = pb1;
    __syncthreads();

    for (int kt = 0; kt < KT; kt++) {
        if (kt + 1 < KT) {
            int k0 = (kt + 1) << 5;
            int r = rowBase + ar0;
            pa0 = (r < M) ? *(const uint4*)(Ab + (size_t)r * Kp + k0 + akc0 * 8) : zero4;
            r = rowBase + ar1;
            pa1 = (r < M) ? *(const uint4*)(Ab + (size_t)r * Kp + k0 + akc1 * 8) : zero4;
            pb0 = *(const uint4*)(Bb + (size_t)(k0 + br0) * N + colBase + bnc0 * 8);
            pb1 = *(const uint4*)(Bb + (size_t)(k0 + br1) * N + colBase + bnc1 * 8);
        }
        unsigned aOff = aBase + buf * ABUFB;
        unsigned bOff = bBase + buf * BBUFB;
        #pragma unroll
        for (int ks = 0; ks < 32; ks += 16) {
            unsigned af[2][4];
            #pragma unroll
            for (int mf = 0; mf < 2; mf++) {
                unsigned addr = aOff +
                    (((wm + mf * 16 + (lane & 15)) * APITCH) + ks + ((lane >> 4) << 3)) * 2;
                ldsm4(af[mf][0], af[mf][1], af[mf][2], af[mf][3], addr);
            }
            #pragma unroll
            for (int p = 0; p < 4; p++) {
                unsigned bfr[4];
                unsigned addr = bOff +
                    (((ks + (lane & 15)) * BPITCH) + wn + p * 16 + ((lane >> 4) << 3)) * 2;
                ldsm4t(bfr[0], bfr[1], bfr[2], bfr[3], addr);
                #pragma unroll
                for (int mf = 0; mf < 2; mf++) {
                    mma16816(cf[mf][2 * p],     af[mf], bfr[0], bfr[1]);
                    mma16816(cf[mf][2 * p + 1], af[mf], bfr[2], bfr[3]);
                }
            }
        }
        if (kt + 1 < KT) {
            int nb = buf ^ 1;
            *(uint4*)(&As[nb][ar0 * APITCH + akc0 * 8]) = pa0;
            *(uint4*)(&As[nb][ar1 * APITCH + akc1 * 8]) = pa1;
            *(uint4*)(&Bs[nb][br0 * BPITCH + bnc0 * 8]) = pb0;
            *(uint4*)(&Bs[nb][br1 * BPITCH + bnc1 * 8]) = pb1;
            __syncthreads();
            buf = nb;
        }
    }

    #pragma unroll
    for (int mf = 0; mf < 2; mf++) {
        int row0 = rowBase + wm + mf * 16 + g;
        int row1 = row0 + 8;
        #pragma unroll
        for (int nf = 0; nf < 8; nf++) {
            int col = colBase + wn + nf * 8 + qp * 2;
            float b0 = 0.f, b1 = 0.f;
            if (bias) { b0 = bias[col]; b1 = bias[col + 1]; }
            if (MODE == 0) {
                if (row0 < M)
                    *(float2*)(C + (size_t)row0 * N + col) =
                        make_float2(cf[mf][nf][0] + b0, cf[mf][nf][1] + b1);
                if (row1 < M)
                    *(float2*)(C + (size_t)row1 * N + col) =
                        make_float2(cf[mf][nf][2] + b0, cf[mf][nf][3] + b1);
            } else {
                float sc0 = bg[col]     * rsqrtf(bv[col]     + 1e-5f);
                float sc1 = bg[col + 1] * rsqrtf(bv[col + 1] + 1e-5f);
                float sh0 = bbe[col],     mm0 = bm[col];
                float sh1 = bbe[col + 1], mm1 = bm[col + 1];
                float y00 = sc0 * (cf[mf][nf][0] + b0 - mm0) + sh0;
                float y01 = sc1 * (cf[mf][nf][1] + b1 - mm1) + sh1;
                float y10 = sc0 * (cf[mf][nf][2] + b0 - mm0) + sh0;
                float y11 = sc1 * (cf[mf][nf][3] + b1 - mm1) + sh1;
                y00 = y00 > 0.f ? y00 : 0.f;
                y01 = y01 > 0.f ? y01 : 0.f;
                y10 = y10 > 0.f ? y10 : 0.f;
                y11 = y11 > 0.f ? y11 : 0.f;
                if (MODE == 1) {
                    if (row0 < M)
                        *(float2*)(C + (size_t)row0 * N + col) = make_float2(y00, y01);
                    if (row1 < M)
                        *(float2*)(C + (size_t)row1 * N + col) = make_float2(y10, y11);
                } else {
                    if (row0 < M) {
                        float2 rr = *(const float2*)(res + (size_t)row0 * N + col);
                        float* pp = pool + (size_t)batch[row0] * N + col;
                        atomicMaxFloat(pp,     y00 + rr.x);
                        atomicMaxFloat(pp + 1, y01 + rr.y);
                    }
                    if (row1 < M) {
                        float2 rr = *(const float2*)(res + (size_t)row1 * N + col);
                        float* pp = pool + (size_t)batch[row1] * N + col;
                        atomicMaxFloat(pp,     y10 + rr.x);
                        atomicMaxFloat(pp + 1, y11 + rr.y);
                    }
                }
            }
        }
    }
}

// ---------------------------------------------------------------------------
// Attention dot products
// ---------------------------------------------------------------------------
__global__ void k_attn_dots(const float* __restrict__ att_s,
                            const float* __restrict__ att_d)
{
    int idx = blockIdx.x * blockDim.x + threadIdx.x;
    if (idx >= NN * HHH) return;
    int n = idx >> 3, h = idx & 7;
    const float* hp = g_h0 + (size_t)n * F1 + h * 32;
    const float* sa = att_s + h * 32;
    const float* da = att_d + h * 32;
    float s = 0.f, d = 0.f;
    #pragma unroll
    for (int c = 0; c < 32; ++c) {
        float hv = hp[c];
        s = fmaf(hv, sa[c], s);
        d = fmaf(hv, da[c], d);
    }
    g_as[idx] = s;
    g_ad[idx] = d;
}

// ---------------------------------------------------------------------------
// Fused GAT: per-node softmax + feature gather + bias + relu.
// Writes h1 fp32 (for GCN1 aggregation) AND bf16 3-term split (for W_res GEMM).
// ---------------------------------------------------------------------------
__global__ __launch_bounds__(256) void k_gat_gather(const float* __restrict__ b_gat) {
    __shared__ float s_alpha[CAP * HHH];
    __shared__ int   s_src[CAP];
    __shared__ float s_ad[HHH];
    __shared__ float s_ms[HHH], s_si[HHH];

    int n = blockIdx.x;
    int start = g_off[n];
    int deg = g_off[n + 1] - start;
    int tid = threadIdx.x;
    int w = tid >> 5, l = tid & 31;

    if (tid < HHH) s_ad[tid] = g_ad[n * HHH + tid];
    int degc = deg < CAP ? deg : CAP;
    for (int i = tid; i < degc; i += 256) s_src[i] = g_csrc[start + i];
    __syncthreads();

    float m = -FLT_MAX, ssum = 0.f;
    float adh = s_ad[w];
    for (int i = l; i < deg; i += 32) {
        int src = (i < CAP) ? s_src[i] : g_csrc[start + i];
        float e = g_as[src * HHH + w] + adh;
        e = (e > 0.f) ? e : 0.2f * e;
        float mn = fmaxf(m, e);
        ssum = ssum * __expf(m - mn) + __expf(e - mn);
        m = mn;
        if (i < CAP) s_alpha[i * HHH + w] = e;
    }
    #pragma unroll
    for (int off = 16; off > 0; off >>= 1) {
        float m2 = __shfl_xor_sync(0xffffffffu, m, off);
        float s2 = __shfl_xor_sync(0xffffffffu, ssum, off);
        float mn = fmaxf(m, m2);
        ssum = ssum * __expf(m - mn) + s2 * __expf(m2 - mn);
        m = mn;
    }
    float inv = 1.0f / ssum;
    for (int i = l; i < degc; i += 32)
        s_alpha[i * HHH + w] = __expf(s_alpha[i * HHH + w] - m) * inv;
    if (l == 0) { s_ms[w] = m; s_si[w] = inv; }
    __syncthreads();

    int h = tid >> 5;
    float acc = 0.f;
    for (int i = 0; i < deg; i++) {
        int src; float alpha;
        if (i < CAP) { src = s_src[i]; alpha = s_alpha[i * HHH + h]; }
        else {
            src = g_csrc[start + i];
            float e = g_as[src * HHH + h] + s_ad[h];
            e = (e > 0.f) ? e : 0.2f * e;
            alpha = __expf(e - s_ms[h]) * s_si[h];
        }
        acc = fmaf(g_h0[(size_t)src * F1 + tid], alpha, acc);
    }
    float v = acc + b_gat[tid];
    v = v > 0.f ? v : 0.f;
    g_h1f[(size_t)n * F1 + tid] = v;
    __nv_bfloat16 hi = __float2bfloat16(v);
    __nv_bfloat16 lo = __float2bfloat16(v - __bfloat162float(hi));
    size_t rb = (size_t)n * (3 * F1);
    g_Ab[rb + tid]            = hi;
    g_Ab[rb + F1 + tid]       = lo;
    g_Ab[rb + 2 * F1 + tid]   = hi;
}

// ---------------------------------------------------------------------------
// GCN aggregation over h1 (256 cols, 1 float/thread): z1 = S@h1.
// Writes z1 directly as bf16 3-term split into g_Ab (stride 768).
// ---------------------------------------------------------------------------
__global__ __launch_bounds__(256) void k_agg_f1() {
    __shared__ int   s_src[CAP];
    __shared__ float s_nrm[CAP];
    int n = blockIdx.x;
    int start = g_off[n];
    int deg = g_off[n + 1] - start;
    int tid = threadIdx.x;
    float dn = g_dinv[n];
    int degc = deg < CAP ? deg : CAP;
    for (int i = tid; i < degc; i += 256) {
        int s = g_csrc[start + i];
        s_src[i] = s;
        s_nrm[i] = g_dinv[s] * g_cw[start + i] * dn;
    }
    __syncthreads();

    float acc = 0.f;
    for (int i = 0; i < deg; i++) {
        int src; float nrm;
        if (i < CAP) { src = s_src[i]; nrm = s_nrm[i]; }
        else {
            src = g_csrc[start + i];
            nrm = g_dinv[src] * g_cw[start + i] * dn;
        }
        acc = fmaf(g_h1f[(size_t)src * F1 + tid], nrm, acc);
    }
    __nv_bfloat16 hi = __float2bfloat16(acc);
    __nv_bfloat16 lo = __float2bfloat16(acc - __bfloat162float(hi));
    size_t rb = (size_t)n * (3 * F1);
    g_Ab[rb + tid]          = hi;
    g_Ab[rb + F1 + tid]     = lo;
    g_Ab[rb + 2 * F1 + tid] = hi;
}

// ---------------------------------------------------------------------------
// GCN aggregation over a1 (512 cols, float2/thread): z2 = S@a1.
// Writes z2 directly as bf16 3-term split into g_Ab (stride 1536).
// ---------------------------------------------------------------------------
__global__ __launch_bounds__(256) void k_agg_f2() {
    __shared__ int   s_src[CAP];
    __shared__ float s_nrm[CAP];
    int n = blockIdx.x;
    int start = g_off[n];
    int deg = g_off[n + 1] - start;
    int tid = threadIdx.x;
    float dn = g_dinv[n];
    int degc = deg < CAP ? deg : CAP;
    for (int i = tid; i < degc; i += 256) {
        int s = g_csrc[start + i];
        s_src[i] = s;
        s_nrm[i] = g_dinv[s] * g_cw[start + i] * dn;
    }
    __syncthreads();

    float2 acc = make_float2(0.f, 0.f);
    for (int i = 0; i < deg; i++) {
        int src; float nrm;
        if (i < CAP) { src = s_src[i]; nrm = s_nrm[i]; }
        else {
            src = g_csrc[start + i];
            nrm = g_dinv[src] * g_cw[start + i] * dn;
        }
        float2 x = *(const float2*)(g_a1f + (size_t)src * F2 + tid * 2);
        acc.x = fmaf(x.x, nrm, acc.x);
        acc.y = fmaf(x.y, nrm, acc.y);
    }
    int j = tid * 2;
    __nv_bfloat162 lo2;
    __nv_bfloat162 hi2 = bsplit_hi2(acc.x, acc.y, lo2);
    size_t rb = (size_t)n * (3 * F2);
    *(__nv_bfloat162*)(g_Ab + rb + j)          = hi2;
    *(__nv_bfloat162*)(g_Ab + rb + F2 + j)     = lo2;
    *(__nv_bfloat162*)(g_Ab + rb + 2 * F2 + j) = hi2;
}

// ---------------------------------------------------------------------------
// MLP head
// ---------------------------------------------------------------------------
__global__ __launch_bounds__(256) void k_head(
    const float* __restrict__ Wf1, const float* __restrict__ bf1,
    const float* __restrict__ Wf2, const float* __restrict__ bf2,
    float* __restrict__ out)
{
    __shared__ float sp[F3];
    __shared__ float sr0[256];
    __shared__ float sr1[256];
    int gb = blockIdx.x, tid = threadIdx.x;
    for (int i = tid; i < F3; i += 256) sp[i] = g_pool[(size_t)gb * F3 + i];
    __syncthreads();

    float acc = bf1[tid];
    #pragma unroll 4
    for (int k = 0; k < F3; ++k)
        acc = fmaf(sp[k], Wf1[(size_t)k * 256 + tid], acc);
    acc = acc > 0.f ? acc : 0.f;

    sr0[tid] = acc * Wf2[tid * 2 + 0];
    sr1[tid] = acc * Wf2[tid * 2 + 1];
    __syncthreads();
    for (int s = 128; s > 0; s >>= 1) {
        if (tid < s) { sr0[tid] += sr0[tid + s]; sr1[tid] += sr1[tid + s]; }
        __syncthreads();
    }
    if (tid == 0) {
        out[gb * 2 + 0] = sr0[0] + bf2[0];
        out[gb * 2 + 1] = sr1[0] + bf2[1];
    }
}

// ---------------------------------------------------------------------------
// Launch
// ---------------------------------------------------------------------------
extern "C" void kernel_launch(void* const* d_in, const int* in_sizes, int n_in,
                              void* d_out, int out_size)
{
    const float* x       = (const float*)d_in[0];
    const int*   ei      = (const int*)  d_in[1];
    const float* ew      = (const float*)d_in[2];
    const int*   batch   = (const int*)  d_in[3];
    const float* W_gat   = (const float*)d_in[4];
    const float* att_src = (const float*)d_in[5];
    const float* att_dst = (const float*)d_in[6];
    const float* b_gat   = (const float*)d_in[7];
    const float* W_res   = (const float*)d_in[8];
    const float* b_res   = (const float*)d_in[9];
    const float* W2      = (const float*)d_in[10];
    const float* b2      = (const float*)d_in[11];
    const float* g1      = (const float*)d_in[12];
    const float* be1     = (const float*)d_in[13];
    const float* m1      = (const float*)d_in[14];
    const float* v1      = (const float*)d_in[15];
    const float* W3      = (const float*)d_in[16];
    const float* b3      = (const float*)d_in[17];
    const float* g2      = (const float*)d_in[18];
    const float* be2     = (const float*)d_in[19];
    const float* m2      = (const float*)d_in[20];
    const float* v2      = (const float*)d_in[21];
    const float* Wf1     = (const float*)d_in[22];
    const float* bf1     = (const float*)d_in[23];
    const float* Wf2     = (const float*)d_in[24];
    const float* bf2     = (const float*)d_in[25];
    float* out = (float*)d_out;

    float *p_h0, *p_res, *p_a1f, *p_pool;
    __nv_bfloat16 *p_Ab, *p_Bb;
    cudaGetSymbolAddress((void**)&p_h0,   g_h0);
    cudaGetSymbolAddress((void**)&p_res,  g_res);
    cudaGetSymbolAddress((void**)&p_a1f,  g_a1f);
    cudaGetSymbolAddress((void**)&p_pool, g_pool);
    cudaGetSymbolAddress((void**)&p_Ab,   g_Ab);
    cudaGetSymbolAddress((void**)&p_Bb,   g_Bb);

    const int rowTiles = (NN + 127) / 128;  // 157
    const int egrid = (EPQ + 255) / 256;

    // CSR build
    k_init<<<512, 256>>>();
    k_count<<<egrid, 256>>>(ei, ew);
    k_scan<<<1, 1024>>>();          // offsets + dinv
    k_fill<<<egrid, 256>>>(ei, ew);

    // GAT: h0 = x @ W_gat   [20000,32]x[32,256]  (bf16 3-term, Kp=96)
    k_splitA<<<2048, 256>>>(x, p_Ab, NN, 32);
    k_splitB<<<64, 256>>>(W_gat, p_Bb, 32, F1);
    gemm_k<0><<<dim3(F1 / 128, rowTiles), 256>>>(
        p_Ab, p_Bb, p_h0, nullptr, nullptr, nullptr, nullptr, nullptr,
        nullptr, nullptr, nullptr, NN, F1, 96);
    k_attn_dots<<<(NN * HHH + 255) / 256, 256>>>(att_src, att_dst);
    k_gat_gather<<<NN, 256>>>(b_gat);   // h1 fp32 + split in g_Ab [NN,768]

    // residual: res = h1 @ W_res + b_res  (uses h1 split)
    k_splitB<<<1024, 256>>>(W_res, p_Bb, F1, F3);
    gemm_k<0><<<dim3(F3 / 128, rowTiles), 256>>>(
        p_Ab, p_Bb, p_res, b_res, nullptr, nullptr, nullptr, nullptr,
        nullptr, nullptr, nullptr, NN, F3, 768);

    // GCN1 reassociated: z1 = S@h1 (256-col gather), a1 = relu(BN1(z1@W2 + b2))
    k_agg_f1<<<NN, 256>>>();            // overwrites g_Ab with z1 split [NN,768]
    k_splitB<<<512, 256>>>(W2, p_Bb, F1, F2);
    gemm_k<1><<<dim3(F2 / 128, rowTiles), 256>>>(
        p_Ab, p_Bb, p_a1f, b2, g1, be1, m1, v1,
        nullptr, nullptr, nullptr, NN, F2, 768);

    // GCN2 reassociated: z2 = S@a1 (512-col gather); final fused epilogue
    k_agg_f2<<<NN, 256>>>();            // writes z2 split [NN,1536]
    k_splitB<<<2048, 256>>>(W3, p_Bb, F2, F3);
    gemm_k<2><<<dim3(F3 / 128, rowTiles), 256>>>(
        p_Ab, p_Bb, nullptr, b3, g2, be2, m2, v2,
        p_res, batch, p_pool, NN, F3, 1536);

    // MLP head
    k_head<<<GGG, 256>>>(Wf1, bf1, Wf2, bf2, out);
}

// round 14
// speedup vs baseline: 1.5360x; 1.0223x over previous
#include <cuda_runtime.h>
#include <cuda_bf16.h>
#include <float.h>
#include <math.h>

// Problem constants
#define NN   20000      // nodes
#define EE   320000     // edges (without self loops)
#define EPQ  340000     // edges + self loops
#define HHH  8          // GAT heads
#define GGG  64         // graphs
#define F1   256        // GAT out (H*32)
#define F2   512        // GCN1 out
#define F3   1024       // GCN2 / residual out
#define CAP  256        // smem edge cache per node

// ---------------------------------------------------------------------------
// Static scratch (no allocations allowed)
// ---------------------------------------------------------------------------
__device__ float g_h0  [NN * F1];     // x @ W_gat
__device__ float g_as  [NN * HHH];
__device__ float g_ad  [NN * HHH];
__device__ float g_h1f [NN * F1];     // GAT output fp32 (for aggregation)
__device__ float g_a1f [NN * F2];     // GCN1 output fp32 (for aggregation)
__device__ float g_res [NN * F3];     // residual branch
__device__ float g_dinv[NN];
__device__ float g_wdeg[NN];
__device__ float g_pool[GGG * F3];
// CSR
__device__ int   g_cnt [NN];
__device__ int   g_off [NN + 1];
__device__ int   g_cur [NN];
__device__ int   g_csrc[EPQ];
__device__ float g_cw  [EPQ];
// split-bf16 3-term GEMM operands:
//   A' = [A_hi | A_lo | A_hi]  (M x 3K, K-major)
//   B' = [B_hi ; B_hi ; B_lo]  (3K x N, row-major)
__device__ __nv_bfloat16 g_Ab[NN * 1536];      // max 3K = 1536
__device__ __nv_bfloat16 g_Bb[1536 * 1024];

// ---------------------------------------------------------------------------
// Helpers
// ---------------------------------------------------------------------------
__device__ __forceinline__ void atomicMaxFloat(float* addr, float val) {
    if (val >= 0.0f) atomicMax((int*)addr, __float_as_int(val));
    else             atomicMin((unsigned int*)addr, __float_as_uint(val));
}

__device__ __forceinline__ void ldsm4(unsigned& r0, unsigned& r1, unsigned& r2, unsigned& r3,
                                      unsigned a) {
    asm volatile("ldmatrix.sync.aligned.m8n8.x4.shared.b16 {%0,%1,%2,%3},[%4];"
                 : "=r"(r0), "=r"(r1), "=r"(r2), "=r"(r3) : "r"(a));
}
__device__ __forceinline__ void ldsm4t(unsigned& r0, unsigned& r1, unsigned& r2, unsigned& r3,
                                       unsigned a) {
    asm volatile("ldmatrix.sync.aligned.m8n8.x4.trans.shared.b16 {%0,%1,%2,%3},[%4];"
                 : "=r"(r0), "=r"(r1), "=r"(r2), "=r"(r3) : "r"(a));
}
__device__ __forceinline__ void mma16816(float* c, const unsigned* a, unsigned b0, unsigned b1) {
    asm volatile(
        "mma.sync.aligned.m16n8k16.row.col.f32.bf16.bf16.f32 "
        "{%0,%1,%2,%3}, {%4,%5,%6,%7}, {%8,%9}, {%0,%1,%2,%3};"
        : "+f"(c[0]), "+f"(c[1]), "+f"(c[2]), "+f"(c[3])
        : "r"(a[0]), "r"(a[1]), "r"(a[2]), "r"(a[3]), "r"(b0), "r"(b1));
}
__device__ __forceinline__ void cpa16(unsigned dst, const void* src, int sz) {
    asm volatile("cp.async.cg.shared.global [%0], [%1], 16, %2;"
                 :: "r"(dst), "l"(src), "r"(sz));
}
__device__ __forceinline__ void cpcommit() { asm volatile("cp.async.commit_group;"); }
template<int W> __device__ __forceinline__ void cpwait() {
    asm volatile("cp.async.wait_group %0;" :: "n"(W));
}

__device__ __forceinline__ __nv_bfloat162 bsplit_hi2(float a, float b,
                                                     __nv_bfloat162& lo2) {
    __nv_bfloat16 h0 = __float2bfloat16(a);
    __nv_bfloat16 h1 = __float2bfloat16(b);
    __nv_bfloat16 l0 = __float2bfloat16(a - __bfloat162float(h0));
    __nv_bfloat16 l1 = __float2bfloat16(b - __bfloat162float(h1));
    __nv_bfloat162 hi2; hi2.x = h0; hi2.y = h1;
    lo2.x = l0; lo2.y = l1;
    return hi2;
}

// ---------------------------------------------------------------------------
// Init
// ---------------------------------------------------------------------------
__global__ void k_init() {
    int i = blockIdx.x * blockDim.x + threadIdx.x;
    int stride = gridDim.x * blockDim.x;
    for (int j = i; j < NN;       j += stride) { g_cnt[j] = 0; g_wdeg[j] = 0.0f; }
    for (int j = i; j < GGG * F3; j += stride) g_pool[j] = -FLT_MAX;
}

// ---------------------------------------------------------------------------
// CSR build
// ---------------------------------------------------------------------------
__global__ void k_count(const int* __restrict__ ei, const float* __restrict__ ew) {
    int e = blockIdx.x * blockDim.x + threadIdx.x;
    if (e >= EPQ) return;
    int dst; float w;
    if (e < EE) { dst = ei[EE + e]; w = ew[e]; }
    else        { dst = e - EE;     w = 1.0f; }
    atomicAdd(&g_cnt[dst], 1);
    atomicAdd(&g_wdeg[dst], w);
}

// 1 block, 1024 threads: exclusive-scan counts (warp-shuffle) + dinv
__global__ void k_scan() {
    __shared__ int wsum[32];
    __shared__ int carry;
    int tid = threadIdx.x, lane = tid & 31, w = tid >> 5;
    if (tid == 0) carry = 0;
    __syncthreads();
    for (int base = 0; base < NN; base += 1024) {
        int i = base + tid;
        int v = (i < NN) ? g_cnt[i] : 0;
        int x = v;
        #pragma unroll
        for (int o = 1; o < 32; o <<= 1) {
            int t = __shfl_up_sync(0xffffffffu, x, o);
            if (lane >= o) x += t;
        }
        if (lane == 31) wsum[w] = x;
        __syncthreads();
        if (w == 0) {
            int s = wsum[lane];
            #pragma unroll
            for (int o = 1; o < 32; o <<= 1) {
                int t = __shfl_up_sync(0xffffffffu, s, o);
                if (lane >= o) s += t;
            }
            wsum[lane] = s;
        }
        __syncthreads();
        int warpoff = (w == 0) ? 0 : wsum[w - 1];
        int excl = carry + warpoff + x - v;
        if (i < NN) {
            g_off[i] = excl;
            g_cur[i] = excl;
            float d = g_wdeg[i];
            g_dinv[i] = (d > 0.f) ? rsqrtf(fmaxf(d, 1e-12f)) : 0.0f;
        }
        __syncthreads();
        if (tid == 0) carry += wsum[31];
        __syncthreads();
    }
    if (tid == 0) g_off[NN] = carry;
}

__global__ void k_fill(const int* __restrict__ ei, const float* __restrict__ ew) {
    int e = blockIdx.x * blockDim.x + threadIdx.x;
    if (e >= EPQ) return;
    int src, dst; float w;
    if (e < EE) { src = ei[e]; dst = ei[EE + e]; w = ew[e]; }
    else        { src = dst = e - EE; w = 1.0f; }
    int slot = atomicAdd(&g_cur[dst], 1);
    g_csrc[slot] = src;
    g_cw[slot]   = w;
}

// ---------------------------------------------------------------------------
// Split fp32 -> bf16 hi/lo operand builders
// ---------------------------------------------------------------------------
__global__ void k_splitA(const float* __restrict__ src, __nv_bfloat16* __restrict__ dst,
                         int M, int K) {
    int stride = gridDim.x * blockDim.x;
    int total = M * K;
    for (int i = blockIdx.x * blockDim.x + threadIdx.x; i < total; i += stride) {
        int row = i / K, k = i - row * K;
        float x = src[i];
        __nv_bfloat16 hi = __float2bfloat16(x);
        __nv_bfloat16 lo = __float2bfloat16(x - __bfloat162float(hi));
        size_t rb = (size_t)row * 3 * K;
        dst[rb + k]         = hi;
        dst[rb + K + k]     = lo;
        dst[rb + 2 * K + k] = hi;
    }
}
__global__ void k_splitB(const float* __restrict__ src, __nv_bfloat16* __restrict__ dst,
                         int K, int N) {
    int stride = gridDim.x * blockDim.x;
    int total = K * N;
    for (int i = blockIdx.x * blockDim.x + threadIdx.x; i < total; i += stride) {
        int k = i / N, n = i - k * N;
        float x = src[i];
        __nv_bfloat16 hi = __float2bfloat16(x);
        __nv_bfloat16 lo = __float2bfloat16(x - __bfloat162float(hi));
        dst[(size_t)k * N + n]           = hi;
        dst[(size_t)(K + k) * N + n]     = hi;
        dst[(size_t)(2 * K + k) * N + n] = lo;
    }
}

// ---------------------------------------------------------------------------
// bf16 tensor-core GEMM, 4-stage cp.async pipeline, templated epilogue:
//  MODE 0: C = v (+bias)
//  MODE 1: C = relu(BN(v+bias))              (fp32 out)
//  MODE 2: y = relu(BN(v+bias)) + res; atomicMax(pool[batch[row]*N+col], y)
// CTA tile 128x128, BK=32, 256 threads (8 warps, warp tile 32x64).
// ---------------------------------------------------------------------------
#define APITCH 40
#define BPITCH 136
#define STAGES 4
#define ASTG   (128 * APITCH * 2)   // 10240 B per A stage
#define BSTG   (32 * BPITCH * 2)    // 8704 B per B stage
#define GSM    (STAGES * (ASTG + BSTG))   // 75776 B dynamic smem

template<int MODE>
__global__ __launch_bounds__(256) void gemm_k(
    const __nv_bfloat16* __restrict__ Ab, const __nv_bfloat16* __restrict__ Bb,
    float* __restrict__ C, const float* __restrict__ bias,
    const float* __restrict__ bg, const float* __restrict__ bbe,
    const float* __restrict__ bm, const float* __restrict__ bv,
    const float* __restrict__ res, const int* __restrict__ batch,
    float* __restrict__ pool,
    int M, int N, int Kp)
{
    extern __shared__ char dsm[];
    unsigned aBase = (unsigned)__cvta_generic_to_shared(dsm);
    unsigned bBase = aBase + STAGES * ASTG;

    int tid = threadIdx.x;
    int wid = tid >> 5, lane = tid & 31;
    int wm = (wid >> 1) * 32;
    int wn = (wid & 1) * 64;
    int g = lane >> 2, qp = lane & 3;
    int rowBase = blockIdx.y * 128;
    int colBase = blockIdx.x * 128;

    float cf[2][8][4];
    #pragma unroll
    for (int mf = 0; mf < 2; mf++)
        #pragma unroll
        for (int nf = 0; nf < 8; nf++)
            #pragma unroll
            for (int q = 0; q < 4; q++) cf[mf][nf][q] = 0.f;

    // load coordinates: A = 512 chunks of 16B (128 rows x 4), B = 512 (32 x 16)
    int ar0 = tid >> 2, akc = tid & 3;      // rows 0..63, +64 for second chunk
    int br0 = tid >> 4, bnc = tid & 15;     // rows 0..15, +16 for second chunk

    #define LOADTILE(kt, st) do {                                              \
        int _k0 = (kt) << 5;                                                   \
        int _r0 = rowBase + ar0;                                               \
        cpa16(aBase + (st) * ASTG + (ar0 * APITCH + akc * 8) * 2,              \
              Ab + (size_t)(_r0 < M ? _r0 : 0) * Kp + _k0 + akc * 8,           \
              _r0 < M ? 16 : 0);                                               \
        int _r1 = _r0 + 64;                                                    \
        cpa16(aBase + (st) * ASTG + ((ar0 + 64) * APITCH + akc * 8) * 2,       \
              Ab + (size_t)(_r1 < M ? _r1 : 0) * Kp + _k0 + akc * 8,           \
              _r1 < M ? 16 : 0);                                               \
        cpa16(bBase + (st) * BSTG + (br0 * BPITCH + bnc * 8) * 2,              \
              Bb + (size_t)(_k0 + br0) * N + colBase + bnc * 8, 16);           \
        cpa16(bBase + (st) * BSTG + ((br0 + 16) * BPITCH + bnc * 8) * 2,       \
              Bb + (size_t)(_k0 + br0 + 16) * N + colBase + bnc * 8, 16);      \
    } while (0)

    int KT = Kp >> 5;
    #pragma unroll
    for (int s = 0; s < STAGES - 1; s++) {
        if (s < KT) LOADTILE(s, s);
        cpcommit();
    }

    for (int kt = 0; kt < KT; kt++) {
        cpwait<STAGES - 2>();
        __syncthreads();
        int nk = kt + STAGES - 1;
        if (nk < KT) LOADTILE(nk, nk & (STAGES - 1));
        cpcommit();

        int st = kt & (STAGES - 1);
        unsigned aOff = aBase + st * ASTG;
        unsigned bOff = bBase + st * BSTG;
        #pragma unroll
        for (int ks = 0; ks < 32; ks += 16) {
            unsigned af[2][4];
            #pragma unroll
            for (int mf = 0; mf < 2; mf++) {
                unsigned addr = aOff +
                    (((wm + mf * 16 + (lane & 15)) * APITCH) + ks + ((lane >> 4) << 3)) * 2;
                ldsm4(af[mf][0], af[mf][1], af[mf][2], af[mf][3], addr);
            }
            #pragma unroll
            for (int p = 0; p < 4; p++) {
                unsigned bfr[4];
                unsigned addr = bOff +
                    (((ks + (lane & 15)) * BPITCH) + wn + p * 16 + ((lane >> 4) << 3)) * 2;
                ldsm4t(bfr[0], bfr[1], bfr[2], bfr[3], addr);
                #pragma unroll
                for (int mf = 0; mf < 2; mf++) {
                    mma16816(cf[mf][2 * p],     af[mf], bfr[0], bfr[1]);
                    mma16816(cf[mf][2 * p + 1], af[mf], bfr[2], bfr[3]);
                }
            }
        }
    }
    #undef LOADTILE

    #pragma unroll
    for (int mf = 0; mf < 2; mf++) {
        int row0 = rowBase + wm + mf * 16 + g;
        int row1 = row0 + 8;
        #pragma unroll
        for (int nf = 0; nf < 8; nf++) {
            int col = colBase + wn + nf * 8 + qp * 2;
            float b0 = 0.f, b1 = 0.f;
            if (bias) { b0 = bias[col]; b1 = bias[col + 1]; }
            if (MODE == 0) {
                if (row0 < M)
                    *(float2*)(C + (size_t)row0 * N + col) =
                        make_float2(cf[mf][nf][0] + b0, cf[mf][nf][1] + b1);
                if (row1 < M)
                    *(float2*)(C + (size_t)row1 * N + col) =
                        make_float2(cf[mf][nf][2] + b0, cf[mf][nf][3] + b1);
            } else {
                float sc0 = bg[col]     * rsqrtf(bv[col]     + 1e-5f);
                float sc1 = bg[col + 1] * rsqrtf(bv[col + 1] + 1e-5f);
                float sh0 = bbe[col],     mm0 = bm[col];
                float sh1 = bbe[col + 1], mm1 = bm[col + 1];
                float y00 = sc0 * (cf[mf][nf][0] + b0 - mm0) + sh0;
                float y01 = sc1 * (cf[mf][nf][1] + b1 - mm1) + sh1;
                float y10 = sc0 * (cf[mf][nf][2] + b0 - mm0) + sh0;
                float y11 = sc1 * (cf[mf][nf][3] + b1 - mm1) + sh1;
                y00 = y00 > 0.f ? y00 : 0.f;
                y01 = y01 > 0.f ? y01 : 0.f;
                y10 = y10 > 0.f ? y10 : 0.f;
                y11 = y11 > 0.f ? y11 : 0.f;
                if (MODE == 1) {
                    if (row0 < M)
                        *(float2*)(C + (size_t)row0 * N + col) = make_float2(y00, y01);
                    if (row1 < M)
                        *(float2*)(C + (size_t)row1 * N + col) = make_float2(y10, y11);
                } else {
                    if (row0 < M) {
                        float2 rr = *(const float2*)(res + (size_t)row0 * N + col);
                        float* pp = pool + (size_t)batch[row0] * N + col;
                        atomicMaxFloat(pp,     y00 + rr.x);
                        atomicMaxFloat(pp + 1, y01 + rr.y);
                    }
                    if (row1 < M) {
                        float2 rr = *(const float2*)(res + (size_t)row1 * N + col);
                        float* pp = pool + (size_t)batch[row1] * N + col;
                        atomicMaxFloat(pp,     y10 + rr.x);
                        atomicMaxFloat(pp + 1, y11 + rr.y);
                    }
                }
            }
        }
    }
}

// ---------------------------------------------------------------------------
// Attention dot products
// ---------------------------------------------------------------------------
__global__ void k_attn_dots(const float* __restrict__ att_s,
                            const float* __restrict__ att_d)
{
    int idx = blockIdx.x * blockDim.x + threadIdx.x;
    if (idx >= NN * HHH) return;
    int n = idx >> 3, h = idx & 7;
    const float* hp = g_h0 + (size_t)n * F1 + h * 32;
    const float* sa = att_s + h * 32;
    const float* da = att_d + h * 32;
    float s = 0.f, d = 0.f;
    #pragma unroll
    for (int c = 0; c < 32; ++c) {
        float hv = hp[c];
        s = fmaf(hv, sa[c], s);
        d = fmaf(hv, da[c], d);
    }
    g_as[idx] = s;
    g_ad[idx] = d;
}

// ---------------------------------------------------------------------------
// Fused GAT: per-node softmax + feature gather + bias + relu.
// Writes h1 fp32 (for GCN1 aggregation) AND bf16 3-term split (for W_res GEMM).
// ---------------------------------------------------------------------------
__global__ __launch_bounds__(256) void k_gat_gather(const float* __restrict__ b_gat) {
    __shared__ float s_alpha[CAP * HHH];
    __shared__ int   s_src[CAP];
    __shared__ float s_ad[HHH];
    __shared__ float s_ms[HHH], s_si[HHH];

    int n = blockIdx.x;
    int start = g_off[n];
    int deg = g_off[n + 1] - start;
    int tid = threadIdx.x;
    int w = tid >> 5, l = tid & 31;

    if (tid < HHH) s_ad[tid] = g_ad[n * HHH + tid];
    int degc = deg < CAP ? deg : CAP;
    for (int i = tid; i < degc; i += 256) s_src[i] = g_csrc[start + i];
    __syncthreads();

    float m = -FLT_MAX, ssum = 0.f;
    float adh = s_ad[w];
    for (int i = l; i < deg; i += 32) {
        int src = (i < CAP) ? s_src[i] : g_csrc[start + i];
        float e = g_as[src * HHH + w] + adh;
        e = (e > 0.f) ? e : 0.2f * e;
        float mn = fmaxf(m, e);
        ssum = ssum * __expf(m - mn) + __expf(e - mn);
        m = mn;
        if (i < CAP) s_alpha[i * HHH + w] = e;
    }
    #pragma unroll
    for (int off = 16; off > 0; off >>= 1) {
        float m2 = __shfl_xor_sync(0xffffffffu, m, off);
        float s2 = __shfl_xor_sync(0xffffffffu, ssum, off);
        float mn = fmaxf(m, m2);
        ssum = ssum * __expf(m - mn) + s2 * __expf(m2 - mn);
        m = mn;
    }
    float inv = 1.0f / ssum;
    for (int i = l; i < degc; i += 32)
        s_alpha[i * HHH + w] = __expf(s_alpha[i * HHH + w] - m) * inv;
    if (l == 0) { s_ms[w] = m; s_si[w] = inv; }
    __syncthreads();

    int h = tid >> 5;
    float acc = 0.f;
    for (int i = 0; i < deg; i++) {
        int src; float alpha;
        if (i < CAP) { src = s_src[i]; alpha = s_alpha[i * HHH + h]; }
        else {
            src = g_csrc[start + i];
            float e = g_as[src * HHH + h] + s_ad[h];
            e = (e > 0.f) ? e : 0.2f * e;
            alpha = __expf(e - s_ms[h]) * s_si[h];
        }
        acc = fmaf(g_h0[(size_t)src * F1 + tid], alpha, acc);
    }
    float v = acc + b_gat[tid];
    v = v > 0.f ? v : 0.f;
    g_h1f[(size_t)n * F1 + tid] = v;
    __nv_bfloat16 hi = __float2bfloat16(v);
    __nv_bfloat16 lo = __float2bfloat16(v - __bfloat162float(hi));
    size_t rb = (size_t)n * (3 * F1);
    g_Ab[rb + tid]            = hi;
    g_Ab[rb + F1 + tid]       = lo;
    g_Ab[rb + 2 * F1 + tid]   = hi;
}

// ---------------------------------------------------------------------------
// GCN aggregation over h1 (256 cols, 1 float/thread): z1 = S@h1 -> split
// ---------------------------------------------------------------------------
__global__ __launch_bounds__(256) void k_agg_f1() {
    __shared__ int   s_src[CAP];
    __shared__ float s_nrm[CAP];
    int n = blockIdx.x;
    int start = g_off[n];
    int deg = g_off[n + 1] - start;
    int tid = threadIdx.x;
    float dn = g_dinv[n];
    int degc = deg < CAP ? deg : CAP;
    for (int i = tid; i < degc; i += 256) {
        int s = g_csrc[start + i];
        s_src[i] = s;
        s_nrm[i] = g_dinv[s] * g_cw[start + i] * dn;
    }
    __syncthreads();

    float acc = 0.f;
    for (int i = 0; i < deg; i++) {
        int src; float nrm;
        if (i < CAP) { src = s_src[i]; nrm = s_nrm[i]; }
        else {
            src = g_csrc[start + i];
            nrm = g_dinv[src] * g_cw[start + i] * dn;
        }
        acc = fmaf(g_h1f[(size_t)src * F1 + tid], nrm, acc);
    }
    __nv_bfloat16 hi = __float2bfloat16(acc);
    __nv_bfloat16 lo = __float2bfloat16(acc - __bfloat162float(hi));
    size_t rb = (size_t)n * (3 * F1);
    g_Ab[rb + tid]          = hi;
    g_Ab[rb + F1 + tid]     = lo;
    g_Ab[rb + 2 * F1 + tid] = hi;
}

// ---------------------------------------------------------------------------
// GCN aggregation over a1 (512 cols, float2/thread): z2 = S@a1 -> split
// ---------------------------------------------------------------------------
__global__ __launch_bounds__(256) void k_agg_f2() {
    __shared__ int   s_src[CAP];
    __shared__ float s_nrm[CAP];
    int n = blockIdx.x;
    int start = g_off[n];
    int deg = g_off[n + 1] - start;
    int tid = threadIdx.x;
    float dn = g_dinv[n];
    int degc = deg < CAP ? deg : CAP;
    for (int i = tid; i < degc; i += 256) {
        int s = g_csrc[start + i];
        s_src[i] = s;
        s_nrm[i] = g_dinv[s] * g_cw[start + i] * dn;
    }
    __syncthreads();

    float2 acc = make_float2(0.f, 0.f);
    for (int i = 0; i < deg; i++) {
        int src; float nrm;
        if (i < CAP) { src = s_src[i]; nrm = s_nrm[i]; }
        else {
            src = g_csrc[start + i];
            nrm = g_dinv[src] * g_cw[start + i] * dn;
        }
        float2 x = *(const float2*)(g_a1f + (size_t)src * F2 + tid * 2);
        acc.x = fmaf(x.x, nrm, acc.x);
        acc.y = fmaf(x.y, nrm, acc.y);
    }
    int j = tid * 2;
    __nv_bfloat162 lo2;
    __nv_bfloat162 hi2 = bsplit_hi2(acc.x, acc.y, lo2);
    size_t rb = (size_t)n * (3 * F2);
    *(__nv_bfloat162*)(g_Ab + rb + j)          = hi2;
    *(__nv_bfloat162*)(g_Ab + rb + F2 + j)     = lo2;
    *(__nv_bfloat162*)(g_Ab + rb + 2 * F2 + j) = hi2;
}

// ---------------------------------------------------------------------------
// MLP head
// ---------------------------------------------------------------------------
__global__ __launch_bounds__(256) void k_head(
    const float* __restrict__ Wf1, const float* __restrict__ bf1,
    const float* __restrict__ Wf2, const float* __restrict__ bf2,
    float* __restrict__ out)
{
    __shared__ float sp[F3];
    __shared__ float sr0[256];
    __shared__ float sr1[256];
    int gb = blockIdx.x, tid = threadIdx.x;
    for (int i = tid; i < F3; i += 256) sp[i] = g_pool[(size_t)gb * F3 + i];
    __syncthreads();

    float acc = bf1[tid];
    #pragma unroll 4
    for (int k = 0; k < F3; ++k)
        acc = fmaf(sp[k], Wf1[(size_t)k * 256 + tid], acc);
    acc = acc > 0.f ? acc : 0.f;

    sr0[tid] = acc * Wf2[tid * 2 + 0];
    sr1[tid] = acc * Wf2[tid * 2 + 1];
    __syncthreads();
    for (int s = 128; s > 0; s >>= 1) {
        if (tid < s) { sr0[tid] += sr0[tid + s]; sr1[tid] += sr1[tid + s]; }
        __syncthreads();
    }
    if (tid == 0) {
        out[gb * 2 + 0] = sr0[0] + bf2[0];
        out[gb * 2 + 1] = sr1[0] + bf2[1];
    }
}

// ---------------------------------------------------------------------------
// Launch
// ---------------------------------------------------------------------------
extern "C" void kernel_launch(void* const* d_in, const int* in_sizes, int n_in,
                              void* d_out, int out_size)
{
    const float* x       = (const float*)d_in[0];
    const int*   ei      = (const int*)  d_in[1];
    const float* ew      = (const float*)d_in[2];
    const int*   batch   = (const int*)  d_in[3];
    const float* W_gat   = (const float*)d_in[4];
    const float* att_src = (const float*)d_in[5];
    const float* att_dst = (const float*)d_in[6];
    const float* b_gat   = (const float*)d_in[7];
    const float* W_res   = (const float*)d_in[8];
    const float* b_res   = (const float*)d_in[9];
    const float* W2      = (const float*)d_in[10];
    const float* b2      = (const float*)d_in[11];
    const float* g1      = (const float*)d_in[12];
    const float* be1     = (const float*)d_in[13];
    const float* m1      = (const float*)d_in[14];
    const float* v1      = (const float*)d_in[15];
    const float* W3      = (const float*)d_in[16];
    const float* b3      = (const float*)d_in[17];
    const float* g2      = (const float*)d_in[18];
    const float* be2     = (const float*)d_in[19];
    const float* m2      = (const float*)d_in[20];
    const float* v2      = (const float*)d_in[21];
    const float* Wf1     = (const float*)d_in[22];
    const float* bf1     = (const float*)d_in[23];
    const float* Wf2     = (const float*)d_in[24];
    const float* bf2     = (const float*)d_in[25];
    float* out = (float*)d_out;

    float *p_h0, *p_res, *p_a1f, *p_pool;
    __nv_bfloat16 *p_Ab, *p_Bb;
    cudaGetSymbolAddress((void**)&p_h0,   g_h0);
    cudaGetSymbolAddress((void**)&p_res,  g_res);
    cudaGetSymbolAddress((void**)&p_a1f,  g_a1f);
    cudaGetSymbolAddress((void**)&p_pool, g_pool);
    cudaGetSymbolAddress((void**)&p_Ab,   g_Ab);
    cudaGetSymbolAddress((void**)&p_Bb,   g_Bb);

    cudaFuncSetAttribute(gemm_k<0>, cudaFuncAttributeMaxDynamicSharedMemorySize, GSM);
    cudaFuncSetAttribute(gemm_k<1>, cudaFuncAttributeMaxDynamicSharedMemorySize, GSM);
    cudaFuncSetAttribute(gemm_k<2>, cudaFuncAttributeMaxDynamicSharedMemorySize, GSM);

    const int rowTiles = (NN + 127) / 128;  // 157
    const int egrid = (EPQ + 255) / 256;

    // CSR build
    k_init<<<512, 256>>>();
    k_count<<<egrid, 256>>>(ei, ew);
    k_scan<<<1, 1024>>>();          // offsets + dinv
    k_fill<<<egrid, 256>>>(ei, ew);

    // GAT: h0 = x @ W_gat   [20000,32]x[32,256]  (bf16 3-term, Kp=96)
    k_splitA<<<2048, 256>>>(x, p_Ab, NN, 32);
    k_splitB<<<64, 256>>>(W_gat, p_Bb, 32, F1);
    gemm_k<0><<<dim3(F1 / 128, rowTiles), 256, GSM>>>(
        p_Ab, p_Bb, p_h0, nullptr, nullptr, nullptr, nullptr, nullptr,
        nullptr, nullptr, nullptr, NN, F1, 96);
    k_attn_dots<<<(NN * HHH + 255) / 256, 256>>>(att_src, att_dst);
    k_gat_gather<<<NN, 256>>>(b_gat);   // h1 fp32 + split in g_Ab [NN,768]

    // residual: res = h1 @ W_res + b_res  (uses h1 split)
    k_splitB<<<1024, 256>>>(W_res, p_Bb, F1, F3);
    gemm_k<0><<<dim3(F3 / 128, rowTiles), 256, GSM>>>(
        p_Ab, p_Bb, p_res, b_res, nullptr, nullptr, nullptr, nullptr,
        nullptr, nullptr, nullptr, NN, F3, 768);

    // GCN1 reassociated: z1 = S@h1 (256-col gather), a1 = relu(BN1(z1@W2 + b2))
    k_agg_f1<<<NN, 256>>>();            // overwrites g_Ab with z1 split [NN,768]
    k_splitB<<<512, 256>>>(W2, p_Bb, F1, F2);
    gemm_k<1><<<dim3(F2 / 128, rowTiles), 256, GSM>>>(
        p_Ab, p_Bb, p_a1f, b2, g1, be1, m1, v1,
        nullptr, nullptr, nullptr, NN, F2, 768);

    // GCN2 reassociated: z2 = S@a1 (512-col gather); final fused epilogue
    k_agg_f2<<<NN, 256>>>();            // writes z2 split [NN,1536]
    k_splitB<<<2048, 256>>>(W3, p_Bb, F2, F3);
    gemm_k<2><<<dim3(F3 / 128, rowTiles), 256, GSM>>>(
        p_Ab, p_Bb, nullptr, b3, g2, be2, m2, v2,
        p_res, batch, p_pool, NN, F3, 1536);

    // MLP head
    k_head<<<GGG, 256>>>(Wf1, bf1, Wf2, bf2, out);
}

// round 15
// speedup vs baseline: 1.6151x; 1.0515x over previous
#include <cuda_runtime.h>
#include <cuda_bf16.h>
#include <float.h>
#include <math.h>

// Problem constants
#define NN   20000      // nodes
#define EE   320000     // edges (without self loops)
#define EPQ  340000     // edges + self loops
#define HHH  8          // GAT heads
#define GGG  64         // graphs
#define F1   256        // GAT out (H*32)
#define F2   512        // GCN1 out
#define F3   1024       // GCN2 / residual out
#define CAP  256        // smem edge cache per node

// ---------------------------------------------------------------------------
// Static scratch (no allocations allowed)
// ---------------------------------------------------------------------------
__device__ float g_h0  [NN * F1];     // x @ W_gat
__device__ float g_as  [NN * HHH];
__device__ float g_ad  [NN * HHH];
__device__ float g_h1f [NN * F1];     // GAT output fp32 (for aggregation)
__device__ float g_a1f [NN * F2];     // GCN1 output fp32 (for aggregation)
__device__ float g_res [NN * F3];     // residual branch
__device__ float g_dinv[NN];
__device__ float g_wdeg[NN];
__device__ float g_pool[GGG * F3];
// CSR
__device__ int   g_cnt [NN];
__device__ int   g_off [NN + 1];
__device__ int   g_cur [NN];
__device__ int   g_csrc[EPQ];
__device__ float g_cw  [EPQ];
// split-bf16 3-term operands (A' = [hi|lo|hi] K-major; B' = [hi;hi;lo] rows)
__device__ __nv_bfloat16 g_Ax [NN * 96];      // x split
__device__ __nv_bfloat16 g_Ab [NN * 768];     // h1 split
__device__ __nv_bfloat16 g_Az1[NN * 768];     // z1 = S@h1 split
__device__ __nv_bfloat16 g_Az2[NN * 1536];    // z2 = S@a1 split
__device__ __nv_bfloat16 g_Bg [96 * 256];     // W_gat split
__device__ __nv_bfloat16 g_Br [768 * 1024];   // W_res split
__device__ __nv_bfloat16 g_B2 [768 * 512];    // W2 split
__device__ __nv_bfloat16 g_B3 [1536 * 1024];  // W3 split

// ---------------------------------------------------------------------------
// Streams / events — created at module load (host-side resources only;
// no device-memory allocation APIs anywhere in kernel_launch).
// ---------------------------------------------------------------------------
static cudaStream_t g_s2;
static cudaEvent_t  g_ev_start, g_ev_csr, g_ev_h1, g_ev_res;
static struct _StreamInit {
    _StreamInit() {
        cudaStreamCreateWithFlags(&g_s2, cudaStreamNonBlocking);
        cudaEventCreateWithFlags(&g_ev_start, cudaEventDisableTiming);
        cudaEventCreateWithFlags(&g_ev_csr,   cudaEventDisableTiming);
        cudaEventCreateWithFlags(&g_ev_h1,    cudaEventDisableTiming);
        cudaEventCreateWithFlags(&g_ev_res,   cudaEventDisableTiming);
    }
} g_stream_init;

// ---------------------------------------------------------------------------
// Helpers
// ---------------------------------------------------------------------------
__device__ __forceinline__ void atomicMaxFloat(float* addr, float val) {
    if (val >= 0.0f) atomicMax((int*)addr, __float_as_int(val));
    else             atomicMin((unsigned int*)addr, __float_as_uint(val));
}

__device__ __forceinline__ void ldsm4(unsigned& r0, unsigned& r1, unsigned& r2, unsigned& r3,
                                      unsigned a) {
    asm volatile("ldmatrix.sync.aligned.m8n8.x4.shared.b16 {%0,%1,%2,%3},[%4];"
                 : "=r"(r0), "=r"(r1), "=r"(r2), "=r"(r3) : "r"(a));
}
__device__ __forceinline__ void ldsm4t(unsigned& r0, unsigned& r1, unsigned& r2, unsigned& r3,
                                       unsigned a) {
    asm volatile("ldmatrix.sync.aligned.m8n8.x4.trans.shared.b16 {%0,%1,%2,%3},[%4];"
                 : "=r"(r0), "=r"(r1), "=r"(r2), "=r"(r3) : "r"(a));
}
__device__ __forceinline__ void mma16816(float* c, const unsigned* a, unsigned b0, unsigned b1) {
    asm volatile(
        "mma.sync.aligned.m16n8k16.row.col.f32.bf16.bf16.f32 "
        "{%0,%1,%2,%3}, {%4,%5,%6,%7}, {%8,%9}, {%0,%1,%2,%3};"
        : "+f"(c[0]), "+f"(c[1]), "+f"(c[2]), "+f"(c[3])
        : "r"(a[0]), "r"(a[1]), "r"(a[2]), "r"(a[3]), "r"(b0), "r"(b1));
}
__device__ __forceinline__ void cpa16(unsigned dst, const void* src, int sz) {
    asm volatile("cp.async.cg.shared.global [%0], [%1], 16, %2;"
                 :: "r"(dst), "l"(src), "r"(sz));
}
__device__ __forceinline__ void cpcommit() { asm volatile("cp.async.commit_group;"); }
template<int W> __device__ __forceinline__ void cpwait() {
    asm volatile("cp.async.wait_group %0;" :: "n"(W));
}

__device__ __forceinline__ __nv_bfloat162 bsplit_hi2(float a, float b,
                                                     __nv_bfloat162& lo2) {
    __nv_bfloat16 h0 = __float2bfloat16(a);
    __nv_bfloat16 h1 = __float2bfloat16(b);
    __nv_bfloat16 l0 = __float2bfloat16(a - __bfloat162float(h0));
    __nv_bfloat16 l1 = __float2bfloat16(b - __bfloat162float(h1));
    __nv_bfloat162 hi2; hi2.x = h0; hi2.y = h1;
    lo2.x = l0; lo2.y = l1;
    return hi2;
}

// ---------------------------------------------------------------------------
// Init
// ---------------------------------------------------------------------------
__global__ void k_init() {
    int i = blockIdx.x * blockDim.x + threadIdx.x;
    int stride = gridDim.x * blockDim.x;
    for (int j = i; j < NN;       j += stride) { g_cnt[j] = 0; g_wdeg[j] = 0.0f; }
    for (int j = i; j < GGG * F3; j += stride) g_pool[j] = -FLT_MAX;
}

// ---------------------------------------------------------------------------
// CSR build
// ---------------------------------------------------------------------------
__global__ void k_count(const int* __restrict__ ei, const float* __restrict__ ew) {
    int e = blockIdx.x * blockDim.x + threadIdx.x;
    if (e >= EPQ) return;
    int dst; float w;
    if (e < EE) { dst = ei[EE + e]; w = ew[e]; }
    else        { dst = e - EE;     w = 1.0f; }
    atomicAdd(&g_cnt[dst], 1);
    atomicAdd(&g_wdeg[dst], w);
}

// 1 block, 1024 threads: exclusive-scan counts (warp-shuffle) + dinv
__global__ void k_scan() {
    __shared__ int wsum[32];
    __shared__ int carry;
    int tid = threadIdx.x, lane = tid & 31, w = tid >> 5;
    if (tid == 0) carry = 0;
    __syncthreads();
    for (int base = 0; base < NN; base += 1024) {
        int i = base + tid;
        int v = (i < NN) ? g_cnt[i] : 0;
        int x = v;
        #pragma unroll
        for (int o = 1; o < 32; o <<= 1) {
            int t = __shfl_up_sync(0xffffffffu, x, o);
            if (lane >= o) x += t;
        }
        if (lane == 31) wsum[w] = x;
        __syncthreads();
        if (w == 0) {
            int s = wsum[lane];
            #pragma unroll
            for (int o = 1; o < 32; o <<= 1) {
                int t = __shfl_up_sync(0xffffffffu, s, o);
                if (lane >= o) s += t;
            }
            wsum[lane] = s;
        }
        __syncthreads();
        int warpoff = (w == 0) ? 0 : wsum[w - 1];
        int excl = carry + warpoff + x - v;
        if (i < NN) {
            g_off[i] = excl;
            g_cur[i] = excl;
            float d = g_wdeg[i];
            g_dinv[i] = (d > 0.f) ? rsqrtf(fmaxf(d, 1e-12f)) : 0.0f;
        }
        __syncthreads();
        if (tid == 0) carry += wsum[31];
        __syncthreads();
    }
    if (tid == 0) g_off[NN] = carry;
}

__global__ void k_fill(const int* __restrict__ ei, const float* __restrict__ ew) {
    int e = blockIdx.x * blockDim.x + threadIdx.x;
    if (e >= EPQ) return;
    int src, dst; float w;
    if (e < EE) { src = ei[e]; dst = ei[EE + e]; w = ew[e]; }
    else        { src = dst = e - EE; w = 1.0f; }
    int slot = atomicAdd(&g_cur[dst], 1);
    g_csrc[slot] = src;
    g_cw[slot]   = w;
}

// ---------------------------------------------------------------------------
// Split fp32 -> bf16 hi/lo operand builders
// ---------------------------------------------------------------------------
__global__ void k_splitA(const float* __restrict__ src, __nv_bfloat16* __restrict__ dst,
                         int M, int K) {
    int stride = gridDim.x * blockDim.x;
    int total = M * K;
    for (int i = blockIdx.x * blockDim.x + threadIdx.x; i < total; i += stride) {
        int row = i / K, k = i - row * K;
        float x = src[i];
        __nv_bfloat16 hi = __float2bfloat16(x);
        __nv_bfloat16 lo = __float2bfloat16(x - __bfloat162float(hi));
        size_t rb = (size_t)row * 3 * K;
        dst[rb + k]         = hi;
        dst[rb + K + k]     = lo;
        dst[rb + 2 * K + k] = hi;
    }
}
__global__ void k_splitB(const float* __restrict__ src, __nv_bfloat16* __restrict__ dst,
                         int K, int N) {
    int stride = gridDim.x * blockDim.x;
    int total = K * N;
    for (int i = blockIdx.x * blockDim.x + threadIdx.x; i < total; i += stride) {
        int k = i / N, n = i - k * N;
        float x = src[i];
        __nv_bfloat16 hi = __float2bfloat16(x);
        __nv_bfloat16 lo = __float2bfloat16(x - __bfloat162float(hi));
        dst[(size_t)k * N + n]           = hi;
        dst[(size_t)(K + k) * N + n]     = hi;
        dst[(size_t)(2 * K + k) * N + n] = lo;
    }
}

// ---------------------------------------------------------------------------
// bf16 tensor-core GEMM, 4-stage cp.async pipeline, templated epilogue:
//  MODE 0: C = v (+bias)
//  MODE 1: C = relu(BN(v+bias))              (fp32 out)
//  MODE 2: y = relu(BN(v+bias)) + res; atomicMax(pool[batch[row]*N+col], y)
// CTA tile 128x128, BK=32, 256 threads (8 warps, warp tile 32x64).
// ---------------------------------------------------------------------------
#define APITCH 40
#define BPITCH 136
#define STAGES 4
#define ASTG   (128 * APITCH * 2)
#define BSTG   (32 * BPITCH * 2)
#define GSM    (STAGES * (ASTG + BSTG))

template<int MODE>
__global__ __launch_bounds__(256) void gemm_k(
    const __nv_bfloat16* __restrict__ Ab, const __nv_bfloat16* __restrict__ Bb,
    float* __restrict__ C, const float* __restrict__ bias,
    const float* __restrict__ bg, const float* __restrict__ bbe,
    const float* __restrict__ bm, const float* __restrict__ bv,
    const float* __restrict__ res, const int* __restrict__ batch,
    float* __restrict__ pool,
    int M, int N, int Kp)
{
    extern __shared__ char dsm[];
    unsigned aBase = (unsigned)__cvta_generic_to_shared(dsm);
    unsigned bBase = aBase + STAGES * ASTG;

    int tid = threadIdx.x;
    int wid = tid >> 5, lane = tid & 31;
    int wm = (wid >> 1) * 32;
    int wn = (wid & 1) * 64;
    int g = lane >> 2, qp = lane & 3;
    int rowBase = blockIdx.y * 128;
    int colBase = blockIdx.x * 128;

    float cf[2][8][4];
    #pragma unroll
    for (int mf = 0; mf < 2; mf++)
        #pragma unroll
        for (int nf = 0; nf < 8; nf++)
            #pragma unroll
            for (int q = 0; q < 4; q++) cf[mf][nf][q] = 0.f;

    int ar0 = tid >> 2, akc = tid & 3;
    int br0 = tid >> 4, bnc = tid & 15;

    #define LOADTILE(kt, st) do {                                              \
        int _k0 = (kt) << 5;                                                   \
        int _r0 = rowBase + ar0;                                               \
        cpa16(aBase + (st) * ASTG + (ar0 * APITCH + akc * 8) * 2,              \
              Ab + (size_t)(_r0 < M ? _r0 : 0) * Kp + _k0 + akc * 8,           \
              _r0 < M ? 16 : 0);                                               \
        int _r1 = _r0 + 64;                                                    \
        cpa16(aBase + (st) * ASTG + ((ar0 + 64) * APITCH + akc * 8) * 2,       \
              Ab + (size_t)(_r1 < M ? _r1 : 0) * Kp + _k0 + akc * 8,           \
              _r1 < M ? 16 : 0);                                               \
        cpa16(bBase + (st) * BSTG + (br0 * BPITCH + bnc * 8) * 2,              \
              Bb + (size_t)(_k0 + br0) * N + colBase + bnc * 8, 16);           \
        cpa16(bBase + (st) * BSTG + ((br0 + 16) * BPITCH + bnc * 8) * 2,       \
              Bb + (size_t)(_k0 + br0 + 16) * N + colBase + bnc * 8, 16);      \
    } while (0)

    int KT = Kp >> 5;
    #pragma unroll
    for (int s = 0; s < STAGES - 1; s++) {
        if (s < KT) LOADTILE(s, s);
        cpcommit();
    }

    for (int kt = 0; kt < KT; kt++) {
        cpwait<STAGES - 2>();
        __syncthreads();
        int nk = kt + STAGES - 1;
        if (nk < KT) LOADTILE(nk, nk & (STAGES - 1));
        cpcommit();

        int st = kt & (STAGES - 1);
        unsigned aOff = aBase + st * ASTG;
        unsigned bOff = bBase + st * BSTG;
        #pragma unroll
        for (int ks = 0; ks < 32; ks += 16) {
            unsigned af[2][4];
            #pragma unroll
            for (int mf = 0; mf < 2; mf++) {
                unsigned addr = aOff +
                    (((wm + mf * 16 + (lane & 15)) * APITCH) + ks + ((lane >> 4) << 3)) * 2;
                ldsm4(af[mf][0], af[mf][1], af[mf][2], af[mf][3], addr);
            }
            #pragma unroll
            for (int p = 0; p < 4; p++) {
                unsigned bfr[4];
                unsigned addr = bOff +
                    (((ks + (lane & 15)) * BPITCH) + wn + p * 16 + ((lane >> 4) << 3)) * 2;
                ldsm4t(bfr[0], bfr[1], bfr[2], bfr[3], addr);
                #pragma unroll
                for (int mf = 0; mf < 2; mf++) {
                    mma16816(cf[mf][2 * p],     af[mf], bfr[0], bfr[1]);
                    mma16816(cf[mf][2 * p + 1], af[mf], bfr[2], bfr[3]);
                }
            }
        }
    }
    #undef LOADTILE

    #pragma unroll
    for (int mf = 0; mf < 2; mf++) {
        int row0 = rowBase + wm + mf * 16 + g;
        int row1 = row0 + 8;
        #pragma unroll
        for (int nf = 0; nf < 8; nf++) {
            int col = colBase + wn + nf * 8 + qp * 2;
            float b0 = 0.f, b1 = 0.f;
            if (bias) { b0 = bias[col]; b1 = bias[col + 1]; }
            if (MODE == 0) {
                if (row0 < M)
                    *(float2*)(C + (size_t)row0 * N + col) =
                        make_float2(cf[mf][nf][0] + b0, cf[mf][nf][1] + b1);
                if (row1 < M)
                    *(float2*)(C + (size_t)row1 * N + col) =
                        make_float2(cf[mf][nf][2] + b0, cf[mf][nf][3] + b1);
            } else {
                float sc0 = bg[col]     * rsqrtf(bv[col]     + 1e-5f);
                float sc1 = bg[col + 1] * rsqrtf(bv[col + 1] + 1e-5f);
                float sh0 = bbe[col],     mm0 = bm[col];
                float sh1 = bbe[col + 1], mm1 = bm[col + 1];
                float y00 = sc0 * (cf[mf][nf][0] + b0 - mm0) + sh0;
                float y01 = sc1 * (cf[mf][nf][1] + b1 - mm1) + sh1;
                float y10 = sc0 * (cf[mf][nf][2] + b0 - mm0) + sh0;
                float y11 = sc1 * (cf[mf][nf][3] + b1 - mm1) + sh1;
                y00 = y00 > 0.f ? y00 : 0.f;
                y01 = y01 > 0.f ? y01 : 0.f;
                y10 = y10 > 0.f ? y10 : 0.f;
                y11 = y11 > 0.f ? y11 : 0.f;
                if (MODE == 1) {
                    if (row0 < M)
                        *(float2*)(C + (size_t)row0 * N + col) = make_float2(y00, y01);
                    if (row1 < M)
                        *(float2*)(C + (size_t)row1 * N + col) = make_float2(y10, y11);
                } else {
                    if (row0 < M) {
                        float2 rr = *(const float2*)(res + (size_t)row0 * N + col);
                        float* pp = pool + (size_t)batch[row0] * N + col;
                        atomicMaxFloat(pp,     y00 + rr.x);
                        atomicMaxFloat(pp + 1, y01 + rr.y);
                    }
                    if (row1 < M) {
                        float2 rr = *(const float2*)(res + (size_t)row1 * N + col);
                        float* pp = pool + (size_t)batch[row1] * N + col;
                        atomicMaxFloat(pp,     y10 + rr.x);
                        atomicMaxFloat(pp + 1, y11 + rr.y);
                    }
                }
            }
        }
    }
}

// ---------------------------------------------------------------------------
// Attention dot products
// ---------------------------------------------------------------------------
__global__ void k_attn_dots(const float* __restrict__ att_s,
                            const float* __restrict__ att_d)
{
    int idx = blockIdx.x * blockDim.x + threadIdx.x;
    if (idx >= NN * HHH) return;
    int n = idx >> 3, h = idx & 7;
    const float* hp = g_h0 + (size_t)n * F1 + h * 32;
    const float* sa = att_s + h * 32;
    const float* da = att_d + h * 32;
    float s = 0.f, d = 0.f;
    #pragma unroll
    for (int c = 0; c < 32; ++c) {
        float hv = hp[c];
        s = fmaf(hv, sa[c], s);
        d = fmaf(hv, da[c], d);
    }
    g_as[idx] = s;
    g_ad[idx] = d;
}

// ---------------------------------------------------------------------------
// Fused GAT: softmax + gather + bias + relu -> h1 fp32 + bf16 split (g_Ab)
// ---------------------------------------------------------------------------
__global__ __launch_bounds__(256) void k_gat_gather(const float* __restrict__ b_gat) {
    __shared__ float s_alpha[CAP * HHH];
    __shared__ int   s_src[CAP];
    __shared__ float s_ad[HHH];
    __shared__ float s_ms[HHH], s_si[HHH];

    int n = blockIdx.x;
    int start = g_off[n];
    int deg = g_off[n + 1] - start;
    int tid = threadIdx.x;
    int w = tid >> 5, l = tid & 31;

    if (tid < HHH) s_ad[tid] = g_ad[n * HHH + tid];
    int degc = deg < CAP ? deg : CAP;
    for (int i = tid; i < degc; i += 256) s_src[i] = g_csrc[start + i];
    __syncthreads();

    float m = -FLT_MAX, ssum = 0.f;
    float adh = s_ad[w];
    for (int i = l; i < deg; i += 32) {
        int src = (i < CAP) ? s_src[i] : g_csrc[start + i];
        float e = g_as[src * HHH + w] + adh;
        e = (e > 0.f) ? e : 0.2f * e;
        float mn = fmaxf(m, e);
        ssum = ssum * __expf(m - mn) + __expf(e - mn);
        m = mn;
        if (i < CAP) s_alpha[i * HHH + w] = e;
    }
    #pragma unroll
    for (int off = 16; off > 0; off >>= 1) {
        float m2 = __shfl_xor_sync(0xffffffffu, m, off);
        float s2 = __shfl_xor_sync(0xffffffffu, ssum, off);
        float mn = fmaxf(m, m2);
        ssum = ssum * __expf(m - mn) + s2 * __expf(m2 - mn);
        m = mn;
    }
    float inv = 1.0f / ssum;
    for (int i = l; i < degc; i += 32)
        s_alpha[i * HHH + w] = __expf(s_alpha[i * HHH + w] - m) * inv;
    if (l == 0) { s_ms[w] = m; s_si[w] = inv; }
    __syncthreads();

    int h = tid >> 5;
    float acc = 0.f;
    for (int i = 0; i < deg; i++) {
        int src; float alpha;
        if (i < CAP) { src = s_src[i]; alpha = s_alpha[i * HHH + h]; }
        else {
            src = g_csrc[start + i];
            float e = g_as[src * HHH + h] + s_ad[h];
            e = (e > 0.f) ? e : 0.2f * e;
            alpha = __expf(e - s_ms[h]) * s_si[h];
        }
        acc = fmaf(g_h0[(size_t)src * F1 + tid], alpha, acc);
    }
    float v = acc + b_gat[tid];
    v = v > 0.f ? v : 0.f;
    g_h1f[(size_t)n * F1 + tid] = v;
    __nv_bfloat16 hi = __float2bfloat16(v);
    __nv_bfloat16 lo = __float2bfloat16(v - __bfloat162float(hi));
    size_t rb = (size_t)n * (3 * F1);
    g_Ab[rb + tid]            = hi;
    g_Ab[rb + F1 + tid]       = lo;
    g_Ab[rb + 2 * F1 + tid]   = hi;
}

// ---------------------------------------------------------------------------
// GCN aggregation over h1 (256 cols): z1 = S@h1 -> split into g_Az1
// ---------------------------------------------------------------------------
__global__ __launch_bounds__(256) void k_agg_f1() {
    __shared__ int   s_src[CAP];
    __shared__ float s_nrm[CAP];
    int n = blockIdx.x;
    int start = g_off[n];
    int deg = g_off[n + 1] - start;
    int tid = threadIdx.x;
    float dn = g_dinv[n];
    int degc = deg < CAP ? deg : CAP;
    for (int i = tid; i < degc; i += 256) {
        int s = g_csrc[start + i];
        s_src[i] = s;
        s_nrm[i] = g_dinv[s] * g_cw[start + i] * dn;
    }
    __syncthreads();

    float acc = 0.f;
    for (int i = 0; i < deg; i++) {
        int src; float nrm;
        if (i < CAP) { src = s_src[i]; nrm = s_nrm[i]; }
        else {
            src = g_csrc[start + i];
            nrm = g_dinv[src] * g_cw[start + i] * dn;
        }
        acc = fmaf(g_h1f[(size_t)src * F1 + tid], nrm, acc);
    }
    __nv_bfloat16 hi = __float2bfloat16(acc);
    __nv_bfloat16 lo = __float2bfloat16(acc - __bfloat162float(hi));
    size_t rb = (size_t)n * (3 * F1);
    g_Az1[rb + tid]          = hi;
    g_Az1[rb + F1 + tid]     = lo;
    g_Az1[rb + 2 * F1 + tid] = hi;
}

// ---------------------------------------------------------------------------
// GCN aggregation over a1 (512 cols): z2 = S@a1 -> split into g_Az2
// ---------------------------------------------------------------------------
__global__ __launch_bounds__(256) void k_agg_f2() {
    __shared__ int   s_src[CAP];
    __shared__ float s_nrm[CAP];
    int n = blockIdx.x;
    int start = g_off[n];
    int deg = g_off[n + 1] - start;
    int tid = threadIdx.x;
    float dn = g_dinv[n];
    int degc = deg < CAP ? deg : CAP;
    for (int i = tid; i < degc; i += 256) {
        int s = g_csrc[start + i];
        s_src[i] = s;
        s_nrm[i] = g_dinv[s] * g_cw[start + i] * dn;
    }
    __syncthreads();

    float2 acc = make_float2(0.f, 0.f);
    for (int i = 0; i < deg; i++) {
        int src; float nrm;
        if (i < CAP) { src = s_src[i]; nrm = s_nrm[i]; }
        else {
            src = g_csrc[start + i];
            nrm = g_dinv[src] * g_cw[start + i] * dn;
        }
        float2 x = *(const float2*)(g_a1f + (size_t)src * F2 + tid * 2);
        acc.x = fmaf(x.x, nrm, acc.x);
        acc.y = fmaf(x.y, nrm, acc.y);
    }
    int j = tid * 2;
    __nv_bfloat162 lo2;
    __nv_bfloat162 hi2 = bsplit_hi2(acc.x, acc.y, lo2);
    size_t rb = (size_t)n * (3 * F2);
    *(__nv_bfloat162*)(g_Az2 + rb + j)          = hi2;
    *(__nv_bfloat162*)(g_Az2 + rb + F2 + j)     = lo2;
    *(__nv_bfloat162*)(g_Az2 + rb + 2 * F2 + j) = hi2;
}

// ---------------------------------------------------------------------------
// MLP head
// ---------------------------------------------------------------------------
__global__ __launch_bounds__(256) void k_head(
    const float* __restrict__ Wf1, const float* __restrict__ bf1,
    const float* __restrict__ Wf2, const float* __restrict__ bf2,
    float* __restrict__ out)
{
    __shared__ float sp[F3];
    __shared__ float sr0[256];
    __shared__ float sr1[256];
    int gb = blockIdx.x, tid = threadIdx.x;
    for (int i = tid; i < F3; i += 256) sp[i] = g_pool[(size_t)gb * F3 + i];
    __syncthreads();

    float acc = bf1[tid];
    #pragma unroll 4
    for (int k = 0; k < F3; ++k)
        acc = fmaf(sp[k], Wf1[(size_t)k * 256 + tid], acc);
    acc = acc > 0.f ? acc : 0.f;

    sr0[tid] = acc * Wf2[tid * 2 + 0];
    sr1[tid] = acc * Wf2[tid * 2 + 1];
    __syncthreads();
    for (int s = 128; s > 0; s >>= 1) {
        if (tid < s) { sr0[tid] += sr0[tid + s]; sr1[tid] += sr1[tid + s]; }
        __syncthreads();
    }
    if (tid == 0) {
        out[gb * 2 + 0] = sr0[0] + bf2[0];
        out[gb * 2 + 1] = sr1[0] + bf2[1];
    }
}

// ---------------------------------------------------------------------------
// Launch — two streams, event fork/join (graph-capture-safe pattern)
// ---------------------------------------------------------------------------
extern "C" void kernel_launch(void* const* d_in, const int* in_sizes, int n_in,
                              void* d_out, int out_size)
{
    const float* x       = (const float*)d_in[0];
    const int*   ei      = (const int*)  d_in[1];
    const float* ew      = (const float*)d_in[2];
    const int*   batch   = (const int*)  d_in[3];
    const float* W_gat   = (const float*)d_in[4];
    const float* att_src = (const float*)d_in[5];
    const float* att_dst = (const float*)d_in[6];
    const float* b_gat   = (const float*)d_in[7];
    const float* W_res   = (const float*)d_in[8];
    const float* b_res   = (const float*)d_in[9];
    const float* W2      = (const float*)d_in[10];
    const float* b2      = (const float*)d_in[11];
    const float* g1      = (const float*)d_in[12];
    const float* be1     = (const float*)d_in[13];
    const float* m1      = (const float*)d_in[14];
    const float* v1      = (const float*)d_in[15];
    const float* W3      = (const float*)d_in[16];
    const float* b3      = (const float*)d_in[17];
    const float* g2      = (const float*)d_in[18];
    const float* be2     = (const float*)d_in[19];
    const float* m2      = (const float*)d_in[20];
    const float* v2      = (const float*)d_in[21];
    const float* Wf1     = (const float*)d_in[22];
    const float* bf1     = (const float*)d_in[23];
    const float* Wf2     = (const float*)d_in[24];
    const float* bf2     = (const float*)d_in[25];
    float* out = (float*)d_out;

    float *p_h0, *p_res, *p_a1f, *p_pool;
    __nv_bfloat16 *p_Ax, *p_Ab, *p_Az1, *p_Az2, *p_Bg, *p_Br, *p_B2, *p_B3;
    cudaGetSymbolAddress((void**)&p_h0,   g_h0);
    cudaGetSymbolAddress((void**)&p_res,  g_res);
    cudaGetSymbolAddress((void**)&p_a1f,  g_a1f);
    cudaGetSymbolAddress((void**)&p_pool, g_pool);
    cudaGetSymbolAddress((void**)&p_Ax,   g_Ax);
    cudaGetSymbolAddress((void**)&p_Ab,   g_Ab);
    cudaGetSymbolAddress((void**)&p_Az1,  g_Az1);
    cudaGetSymbolAddress((void**)&p_Az2,  g_Az2);
    cudaGetSymbolAddress((void**)&p_Bg,   g_Bg);
    cudaGetSymbolAddress((void**)&p_Br,   g_Br);
    cudaGetSymbolAddress((void**)&p_B2,   g_B2);
    cudaGetSymbolAddress((void**)&p_B3,   g_B3);

    cudaFuncSetAttribute(gemm_k<0>, cudaFuncAttributeMaxDynamicSharedMemorySize, GSM);
    cudaFuncSetAttribute(gemm_k<1>, cudaFuncAttributeMaxDynamicSharedMemorySize, GSM);
    cudaFuncSetAttribute(gemm_k<2>, cudaFuncAttributeMaxDynamicSharedMemorySize, GSM);

    const int rowTiles = (NN + 127) / 128;  // 157
    const int egrid = (EPQ + 255) / 256;

    // ---- fork: side stream does CSR build + weight splits -----------------
    cudaEventRecord(g_ev_start, 0);
    cudaStreamWaitEvent(g_s2, g_ev_start, 0);

    k_init <<<512,   256, 0, g_s2>>>();
    k_count<<<egrid, 256, 0, g_s2>>>(ei, ew);
    k_scan <<<1,    1024, 0, g_s2>>>();
    k_fill <<<egrid, 256, 0, g_s2>>>(ei, ew);
    k_splitB<<<1024, 256, 0, g_s2>>>(W_res, p_Br, F1, F3);
    k_splitB<<<512,  256, 0, g_s2>>>(W2,    p_B2, F1, F2);
    k_splitB<<<2048, 256, 0, g_s2>>>(W3,    p_B3, F2, F3);
    cudaEventRecord(g_ev_csr, g_s2);

    // ---- main: GAT GEMM chain (concurrent with side) ----------------------
    k_splitA<<<2048, 256>>>(x, p_Ax, NN, 32);
    k_splitB<<<64,   256>>>(W_gat, p_Bg, 32, F1);
    gemm_k<0><<<dim3(F1 / 128, rowTiles), 256, GSM>>>(
        p_Ax, p_Bg, p_h0, nullptr, nullptr, nullptr, nullptr, nullptr,
        nullptr, nullptr, nullptr, NN, F1, 96);
    k_attn_dots<<<(NN * HHH + 255) / 256, 256>>>(att_src, att_dst);

    cudaStreamWaitEvent(0, g_ev_csr, 0);            // join: need CSR
    k_gat_gather<<<NN, 256>>>(b_gat);               // h1 fp32 + split in g_Ab
    cudaEventRecord(g_ev_h1, 0);

    // ---- fork 2: residual GEMM on side, GCN chain on main -----------------
    cudaStreamWaitEvent(g_s2, g_ev_h1, 0);
    gemm_k<0><<<dim3(F3 / 128, rowTiles), 256, GSM, g_s2>>>(
        p_Ab, p_Br, p_res, b_res, nullptr, nullptr, nullptr, nullptr,
        nullptr, nullptr, nullptr, NN, F3, 768);
    cudaEventRecord(g_ev_res, g_s2);

    k_agg_f1<<<NN, 256>>>();                        // z1 split -> g_Az1
    gemm_k<1><<<dim3(F2 / 128, rowTiles), 256, GSM>>>(
        p_Az1, p_B2, p_a1f, b2, g1, be1, m1, v1,
        nullptr, nullptr, nullptr, NN, F2, 768);
    k_agg_f2<<<NN, 256>>>();                        // z2 split -> g_Az2

    cudaStreamWaitEvent(0, g_ev_res, 0);            // join: need g_res
    gemm_k<2><<<dim3(F3 / 128, rowTiles), 256, GSM>>>(
        p_Az2, p_B3, nullptr, b3, g2, be2, m2, v2,
        p_res, batch, p_pool, NN, F3, 1536);

    // MLP head
    k_head<<<GGG, 256>>>(Wf1, bf1, Wf2, bf2, out);
}

// round 16
// speedup vs baseline: 1.9743x; 1.2224x over previous
#include <cuda_runtime.h>
#include <cuda_bf16.h>
#include <float.h>
#include <math.h>

// Problem constants
#define NN   20000      // nodes
#define EE   320000     // edges (without self loops)
#define EPQ  340000     // edges + self loops
#define HHH  8          // GAT heads
#define GGG  64         // graphs
#define F1   256        // GAT out (H*32)
#define F2   512        // GCN1 out
#define F3   1024       // GCN2 / residual out
#define CAP  256        // smem edge cache per node

// ---------------------------------------------------------------------------
// Static scratch (no allocations allowed)
// ---------------------------------------------------------------------------
__device__ float g_h0  [NN * F1];     // x @ W_gat
__device__ float g_as  [NN * HHH];
__device__ float g_ad  [NN * HHH];
__device__ float g_h1f [NN * F1];     // GAT output fp32 (for aggregation)
__device__ float g_a1f [NN * F2];     // GCN1 output fp32 (for aggregation)
__device__ float g_res [NN * F3];     // residual branch
__device__ float g_dinv[NN];
__device__ float g_wdeg[NN];
__device__ float g_pool[GGG * F3];
// CSR
__device__ int   g_cnt [NN];
__device__ int   g_off [NN + 1];
__device__ int   g_cur [NN];
__device__ int   g_csrc[EPQ];
__device__ float g_cw  [EPQ];
// split-bf16 3-term operands (A' = [hi|lo|hi] K-major; B' = [hi;hi;lo] rows)
__device__ __nv_bfloat16 g_Ax [NN * 96];      // x split
__device__ __nv_bfloat16 g_Ab [NN * 768];     // h1 split
__device__ __nv_bfloat16 g_Az1[NN * 768];     // z1 = S@h1 split
__device__ __nv_bfloat16 g_Az2[NN * 1536];    // z2 = S@a1 split
__device__ __nv_bfloat16 g_Bg [96 * 256];     // W_gat split
__device__ __nv_bfloat16 g_Br [768 * 1024];   // W_res split
__device__ __nv_bfloat16 g_B2 [768 * 512];    // W2 split
__device__ __nv_bfloat16 g_B3 [1536 * 1024];  // W3 split

// ---------------------------------------------------------------------------
// Streams / events — created at module load (host-side resources only)
// ---------------------------------------------------------------------------
static cudaStream_t g_s2;
static cudaEvent_t  g_ev_start, g_ev_csr, g_ev_h1, g_ev_res;
static struct _StreamInit {
    _StreamInit() {
        cudaStreamCreateWithFlags(&g_s2, cudaStreamNonBlocking);
        cudaEventCreateWithFlags(&g_ev_start, cudaEventDisableTiming);
        cudaEventCreateWithFlags(&g_ev_csr,   cudaEventDisableTiming);
        cudaEventCreateWithFlags(&g_ev_h1,    cudaEventDisableTiming);
        cudaEventCreateWithFlags(&g_ev_res,   cudaEventDisableTiming);
    }
} g_stream_init;

// ---------------------------------------------------------------------------
// Helpers
// ---------------------------------------------------------------------------
__device__ __forceinline__ void atomicMaxFloat(float* addr, float val) {
    if (val >= 0.0f) atomicMax((int*)addr, __float_as_int(val));
    else             atomicMin((unsigned int*)addr, __float_as_uint(val));
}

__device__ __forceinline__ void ldsm4(unsigned& r0, unsigned& r1, unsigned& r2, unsigned& r3,
                                      unsigned a) {
    asm volatile("ldmatrix.sync.aligned.m8n8.x4.shared.b16 {%0,%1,%2,%3},[%4];"
                 : "=r"(r0), "=r"(r1), "=r"(r2), "=r"(r3) : "r"(a));
}
__device__ __forceinline__ void ldsm4t(unsigned& r0, unsigned& r1, unsigned& r2, unsigned& r3,
                                       unsigned a) {
    asm volatile("ldmatrix.sync.aligned.m8n8.x4.trans.shared.b16 {%0,%1,%2,%3},[%4];"
                 : "=r"(r0), "=r"(r1), "=r"(r2), "=r"(r3) : "r"(a));
}
__device__ __forceinline__ void mma16816(float* c, const unsigned* a, unsigned b0, unsigned b1) {
    asm volatile(
        "mma.sync.aligned.m16n8k16.row.col.f32.bf16.bf16.f32 "
        "{%0,%1,%2,%3}, {%4,%5,%6,%7}, {%8,%9}, {%0,%1,%2,%3};"
        : "+f"(c[0]), "+f"(c[1]), "+f"(c[2]), "+f"(c[3])
        : "r"(a[0]), "r"(a[1]), "r"(a[2]), "r"(a[3]), "r"(b0), "r"(b1));
}
__device__ __forceinline__ void cpa16(unsigned dst, const void* src, int sz) {
    asm volatile("cp.async.cg.shared.global [%0], [%1], 16, %2;"
                 :: "r"(dst), "l"(src), "r"(sz));
}
__device__ __forceinline__ void cpcommit() { asm volatile("cp.async.commit_group;"); }
template<int W> __device__ __forceinline__ void cpwait() {
    asm volatile("cp.async.wait_group %0;" :: "n"(W));
}

__device__ __forceinline__ __nv_bfloat162 bsplit_hi2(float a, float b,
                                                     __nv_bfloat162& lo2) {
    __nv_bfloat16 h0 = __float2bfloat16(a);
    __nv_bfloat16 h1 = __float2bfloat16(b);
    __nv_bfloat16 l0 = __float2bfloat16(a - __bfloat162float(h0));
    __nv_bfloat16 l1 = __float2bfloat16(b - __bfloat162float(h1));
    __nv_bfloat162 hi2; hi2.x = h0; hi2.y = h1;
    lo2.x = l0; lo2.y = l1;
    return hi2;
}

// ---------------------------------------------------------------------------
// Init
// ---------------------------------------------------------------------------
__global__ void k_init() {
    int i = blockIdx.x * blockDim.x + threadIdx.x;
    int stride = gridDim.x * blockDim.x;
    for (int j = i; j < NN;       j += stride) { g_cnt[j] = 0; g_wdeg[j] = 0.0f; }
    for (int j = i; j < GGG * F3; j += stride) g_pool[j] = -FLT_MAX;
}

// ---------------------------------------------------------------------------
// CSR build
// ---------------------------------------------------------------------------
__global__ void k_count(const int* __restrict__ ei, const float* __restrict__ ew) {
    int e = blockIdx.x * blockDim.x + threadIdx.x;
    if (e >= EPQ) return;
    int dst; float w;
    if (e < EE) { dst = ei[EE + e]; w = ew[e]; }
    else        { dst = e - EE;     w = 1.0f; }
    atomicAdd(&g_cnt[dst], 1);
    atomicAdd(&g_wdeg[dst], w);
}

// 1 block, 1024 threads: exclusive-scan counts (warp-shuffle) + dinv
__global__ void k_scan() {
    __shared__ int wsum[32];
    __shared__ int carry;
    int tid = threadIdx.x, lane = tid & 31, w = tid >> 5;
    if (tid == 0) carry = 0;
    __syncthreads();
    for (int base = 0; base < NN; base += 1024) {
        int i = base + tid;
        int v = (i < NN) ? g_cnt[i] : 0;
        int x = v;
        #pragma unroll
        for (int o = 1; o < 32; o <<= 1) {
            int t = __shfl_up_sync(0xffffffffu, x, o);
            if (lane >= o) x += t;
        }
        if (lane == 31) wsum[w] = x;
        __syncthreads();
        if (w == 0) {
            int s = wsum[lane];
            #pragma unroll
            for (int o = 1; o < 32; o <<= 1) {
                int t = __shfl_up_sync(0xffffffffu, s, o);
                if (lane >= o) s += t;
            }
            wsum[lane] = s;
        }
        __syncthreads();
        int warpoff = (w == 0) ? 0 : wsum[w - 1];
        int excl = carry + warpoff + x - v;
        if (i < NN) {
            g_off[i] = excl;
            g_cur[i] = excl;
            float d = g_wdeg[i];
            g_dinv[i] = (d > 0.f) ? rsqrtf(fmaxf(d, 1e-12f)) : 0.0f;
        }
        __syncthreads();
        if (tid == 0) carry += wsum[31];
        __syncthreads();
    }
    if (tid == 0) g_off[NN] = carry;
}

__global__ void k_fill(const int* __restrict__ ei, const float* __restrict__ ew) {
    int e = blockIdx.x * blockDim.x + threadIdx.x;
    if (e >= EPQ) return;
    int src, dst; float w;
    if (e < EE) { src = ei[e]; dst = ei[EE + e]; w = ew[e]; }
    else        { src = dst = e - EE; w = 1.0f; }
    int slot = atomicAdd(&g_cur[dst], 1);
    g_csrc[slot] = src;
    g_cw[slot]   = w;
}

// ---------------------------------------------------------------------------
// Split fp32 -> bf16 hi/lo operand builders
// ---------------------------------------------------------------------------
__global__ void k_splitA(const float* __restrict__ src, __nv_bfloat16* __restrict__ dst,
                         int M, int K) {
    int stride = gridDim.x * blockDim.x;
    int total = M * K;
    for (int i = blockIdx.x * blockDim.x + threadIdx.x; i < total; i += stride) {
        int row = i / K, k = i - row * K;
        float x = src[i];
        __nv_bfloat16 hi = __float2bfloat16(x);
        __nv_bfloat16 lo = __float2bfloat16(x - __bfloat162float(hi));
        size_t rb = (size_t)row * 3 * K;
        dst[rb + k]         = hi;
        dst[rb + K + k]     = lo;
        dst[rb + 2 * K + k] = hi;
    }
}
__global__ void k_splitB(const float* __restrict__ src, __nv_bfloat16* __restrict__ dst,
                         int K, int N) {
    int stride = gridDim.x * blockDim.x;
    int total = K * N;
    for (int i = blockIdx.x * blockDim.x + threadIdx.x; i < total; i += stride) {
        int k = i / N, n = i - k * N;
        float x = src[i];
        __nv_bfloat16 hi = __float2bfloat16(x);
        __nv_bfloat16 lo = __float2bfloat16(x - __bfloat162float(hi));
        dst[(size_t)k * N + n]           = hi;
        dst[(size_t)(K + k) * N + n]     = hi;
        dst[(size_t)(2 * K + k) * N + n] = lo;
    }
}

// ---------------------------------------------------------------------------
// bf16 tensor-core GEMM, 4-stage cp.async pipeline, templated epilogue.
// __launch_bounds__(256, 2): force <=128 regs so 2 CTAs/SM co-reside.
// ---------------------------------------------------------------------------
#define APITCH 40
#define BPITCH 136
#define STAGES 4
#define ASTG   (128 * APITCH * 2)
#define BSTG   (32 * BPITCH * 2)
#define GSM    (STAGES * (ASTG + BSTG))

template<int MODE>
__global__ __launch_bounds__(256, 2) void gemm_k(
    const __nv_bfloat16* __restrict__ Ab, const __nv_bfloat16* __restrict__ Bb,
    float* __restrict__ C, const float* __restrict__ bias,
    const float* __restrict__ bg, const float* __restrict__ bbe,
    const float* __restrict__ bm, const float* __restrict__ bv,
    const float* __restrict__ res, const int* __restrict__ batch,
    float* __restrict__ pool,
    int M, int N, int Kp)
{
    extern __shared__ char dsm[];
    unsigned aBase = (unsigned)__cvta_generic_to_shared(dsm);
    unsigned bBase = aBase + STAGES * ASTG;

    int tid = threadIdx.x;
    int wid = tid >> 5, lane = tid & 31;
    int wm = (wid >> 1) * 32;
    int wn = (wid & 1) * 64;
    int g = lane >> 2, qp = lane & 3;
    int rowBase = blockIdx.y * 128;
    int colBase = blockIdx.x * 128;

    float cf[2][8][4];
    #pragma unroll
    for (int mf = 0; mf < 2; mf++)
        #pragma unroll
        for (int nf = 0; nf < 8; nf++)
            #pragma unroll
            for (int q = 0; q < 4; q++) cf[mf][nf][q] = 0.f;

    int ar0 = tid >> 2, akc = tid & 3;
    int br0 = tid >> 4, bnc = tid & 15;

    #define LOADTILE(kt, st) do {                                              \
        int _k0 = (kt) << 5;                                                   \
        int _r0 = rowBase + ar0;                                               \
        cpa16(aBase + (st) * ASTG + (ar0 * APITCH + akc * 8) * 2,              \
              Ab + (size_t)(_r0 < M ? _r0 : 0) * Kp + _k0 + akc * 8,           \
              _r0 < M ? 16 : 0);                                               \
        int _r1 = _r0 + 64;                                                    \
        cpa16(aBase + (st) * ASTG + ((ar0 + 64) * APITCH + akc * 8) * 2,       \
              Ab + (size_t)(_r1 < M ? _r1 : 0) * Kp + _k0 + akc * 8,           \
              _r1 < M ? 16 : 0);                                               \
        cpa16(bBase + (st) * BSTG + (br0 * BPITCH + bnc * 8) * 2,              \
              Bb + (size_t)(_k0 + br0) * N + colBase + bnc * 8, 16);           \
        cpa16(bBase + (st) * BSTG + ((br0 + 16) * BPITCH + bnc * 8) * 2,       \
              Bb + (size_t)(_k0 + br0 + 16) * N + colBase + bnc * 8, 16);      \
    } while (0)

    int KT = Kp >> 5;
    #pragma unroll
    for (int s = 0; s < STAGES - 1; s++) {
        if (s < KT) LOADTILE(s, s);
        cpcommit();
    }

    for (int kt = 0; kt < KT; kt++) {
        cpwait<STAGES - 2>();
        __syncthreads();
        int nk = kt + STAGES - 1;
        if (nk < KT) LOADTILE(nk, nk & (STAGES - 1));
        cpcommit();

        int st = kt & (STAGES - 1);
        unsigned aOff = aBase + st * ASTG;
        unsigned bOff = bBase + st * BSTG;
        #pragma unroll
        for (int ks = 0; ks < 32; ks += 16) {
            unsigned af[2][4];
            #pragma unroll
            for (int mf = 0; mf < 2; mf++) {
                unsigned addr = aOff +
                    (((wm + mf * 16 + (lane & 15)) * APITCH) + ks + ((lane >> 4) << 3)) * 2;
                ldsm4(af[mf][0], af[mf][1], af[mf][2], af[mf][3], addr);
            }
            #pragma unroll
            for (int p = 0; p < 4; p++) {
                unsigned bfr[4];
                unsigned addr = bOff +
                    (((ks + (lane & 15)) * BPITCH) + wn + p * 16 + ((lane >> 4) << 3)) * 2;
                ldsm4t(bfr[0], bfr[1], bfr[2], bfr[3], addr);
                #pragma unroll
                for (int mf = 0; mf < 2; mf++) {
                    mma16816(cf[mf][2 * p],     af[mf], bfr[0], bfr[1]);
                    mma16816(cf[mf][2 * p + 1], af[mf], bfr[2], bfr[3]);
                }
            }
        }
    }
    #undef LOADTILE

    #pragma unroll
    for (int mf = 0; mf < 2; mf++) {
        int row0 = rowBase + wm + mf * 16 + g;
        int row1 = row0 + 8;
        #pragma unroll
        for (int nf = 0; nf < 8; nf++) {
            int col = colBase + wn + nf * 8 + qp * 2;
            float b0 = 0.f, b1 = 0.f;
            if (bias) { b0 = bias[col]; b1 = bias[col + 1]; }
            if (MODE == 0) {
                if (row0 < M)
                    *(float2*)(C + (size_t)row0 * N + col) =
                        make_float2(cf[mf][nf][0] + b0, cf[mf][nf][1] + b1);
                if (row1 < M)
                    *(float2*)(C + (size_t)row1 * N + col) =
                        make_float2(cf[mf][nf][2] + b0, cf[mf][nf][3] + b1);
            } else {
                float sc0 = bg[col]     * rsqrtf(bv[col]     + 1e-5f);
                float sc1 = bg[col + 1] * rsqrtf(bv[col + 1] + 1e-5f);
                float sh0 = bbe[col],     mm0 = bm[col];
                float sh1 = bbe[col + 1], mm1 = bm[col + 1];
                float y00 = sc0 * (cf[mf][nf][0] + b0 - mm0) + sh0;
                float y01 = sc1 * (cf[mf][nf][1] + b1 - mm1) + sh1;
                float y10 = sc0 * (cf[mf][nf][2] + b0 - mm0) + sh0;
                float y11 = sc1 * (cf[mf][nf][3] + b1 - mm1) + sh1;
                y00 = y00 > 0.f ? y00 : 0.f;
                y01 = y01 > 0.f ? y01 : 0.f;
                y10 = y10 > 0.f ? y10 : 0.f;
                y11 = y11 > 0.f ? y11 : 0.f;
                if (MODE == 1) {
                    if (row0 < M)
                        *(float2*)(C + (size_t)row0 * N + col) = make_float2(y00, y01);
                    if (row1 < M)
                        *(float2*)(C + (size_t)row1 * N + col) = make_float2(y10, y11);
                } else {
                    if (row0 < M) {
                        float2 rr = *(const float2*)(res + (size_t)row0 * N + col);
                        float* pp = pool + (size_t)batch[row0] * N + col;
                        atomicMaxFloat(pp,     y00 + rr.x);
                        atomicMaxFloat(pp + 1, y01 + rr.y);
                    }
                    if (row1 < M) {
                        float2 rr = *(const float2*)(res + (size_t)row1 * N + col);
                        float* pp = pool + (size_t)batch[row1] * N + col;
                        atomicMaxFloat(pp,     y10 + rr.x);
                        atomicMaxFloat(pp + 1, y11 + rr.y);
                    }
                }
            }
        }
    }
}

// ---------------------------------------------------------------------------
// Attention dot products
// ---------------------------------------------------------------------------
__global__ void k_attn_dots(const float* __restrict__ att_s,
                            const float* __restrict__ att_d)
{
    int idx = blockIdx.x * blockDim.x + threadIdx.x;
    if (idx >= NN * HHH) return;
    int n = idx >> 3, h = idx & 7;
    const float* hp = g_h0 + (size_t)n * F1 + h * 32;
    const float* sa = att_s + h * 32;
    const float* da = att_d + h * 32;
    float s = 0.f, d = 0.f;
    #pragma unroll
    for (int c = 0; c < 32; ++c) {
        float hv = hp[c];
        s = fmaf(hv, sa[c], s);
        d = fmaf(hv, da[c], d);
    }
    g_as[idx] = s;
    g_ad[idx] = d;
}

// ---------------------------------------------------------------------------
// Fused GAT: softmax + gather + bias + relu -> h1 fp32 + bf16 split (g_Ab)
// Fast-path edge loop (deg<=CAP) is branch-free and unrolled x2.
// ---------------------------------------------------------------------------
__global__ __launch_bounds__(256) void k_gat_gather(const float* __restrict__ b_gat) {
    __shared__ float s_alpha[CAP * HHH];
    __shared__ int   s_src[CAP];
    __shared__ float s_ad[HHH];
    __shared__ float s_ms[HHH], s_si[HHH];

    int n = blockIdx.x;
    int start = g_off[n];
    int deg = g_off[n + 1] - start;
    int tid = threadIdx.x;
    int w = tid >> 5, l = tid & 31;

    if (tid < HHH) s_ad[tid] = g_ad[n * HHH + tid];
    int degc = deg < CAP ? deg : CAP;
    for (int i = tid; i < degc; i += 256) s_src[i] = g_csrc[start + i];
    __syncthreads();

    float m = -FLT_MAX, ssum = 0.f;
    float adh = s_ad[w];
    for (int i = l; i < deg; i += 32) {
        int src = (i < CAP) ? s_src[i] : g_csrc[start + i];
        float e = g_as[src * HHH + w] + adh;
        e = (e > 0.f) ? e : 0.2f * e;
        float mn = fmaxf(m, e);
        ssum = ssum * __expf(m - mn) + __expf(e - mn);
        m = mn;
        if (i < CAP) s_alpha[i * HHH + w] = e;
    }
    #pragma unroll
    for (int off = 16; off > 0; off >>= 1) {
        float m2 = __shfl_xor_sync(0xffffffffu, m, off);
        float s2 = __shfl_xor_sync(0xffffffffu, ssum, off);
        float mn = fmaxf(m, m2);
        ssum = ssum * __expf(m - mn) + s2 * __expf(m2 - mn);
        m = mn;
    }
    float inv = 1.0f / ssum;
    for (int i = l; i < degc; i += 32)
        s_alpha[i * HHH + w] = __expf(s_alpha[i * HHH + w] - m) * inv;
    if (l == 0) { s_ms[w] = m; s_si[w] = inv; }
    __syncthreads();

    int h = tid >> 5;
    const float* h0col = g_h0 + tid;
    float acc = 0.f;
    int i = 0;
    // fast path: edges cached in smem, unrolled x2 for MLP
    for (; i + 1 < degc; i += 2) {
        int s0 = s_src[i],     s1 = s_src[i + 1];
        float a0 = s_alpha[i * HHH + h];
        float a1 = s_alpha[(i + 1) * HHH + h];
        float x0 = h0col[(size_t)s0 * F1];
        float x1 = h0col[(size_t)s1 * F1];
        acc = fmaf(x0, a0, acc);
        acc = fmaf(x1, a1, acc);
    }
    for (; i < deg; i++) {
        int src; float alpha;
        if (i < CAP) { src = s_src[i]; alpha = s_alpha[i * HHH + h]; }
        else {
            src = g_csrc[start + i];
            float e = g_as[src * HHH + h] + s_ad[h];
            e = (e > 0.f) ? e : 0.2f * e;
            alpha = __expf(e - s_ms[h]) * s_si[h];
        }
        acc = fmaf(h0col[(size_t)src * F1], alpha, acc);
    }
    float v = acc + b_gat[tid];
    v = v > 0.f ? v : 0.f;
    g_h1f[(size_t)n * F1 + tid] = v;
    __nv_bfloat16 hi = __float2bfloat16(v);
    __nv_bfloat16 lo = __float2bfloat16(v - __bfloat162float(hi));
    size_t rb = (size_t)n * (3 * F1);
    g_Ab[rb + tid]            = hi;
    g_Ab[rb + F1 + tid]       = lo;
    g_Ab[rb + 2 * F1 + tid]   = hi;
}

// ---------------------------------------------------------------------------
// GCN aggregation over h1 (256 cols): z1 = S@h1 -> split into g_Az1
// Fast path unrolled x4.
// ---------------------------------------------------------------------------
__global__ __launch_bounds__(256) void k_agg_f1() {
    __shared__ int   s_src[CAP];
    __shared__ float s_nrm[CAP];
    int n = blockIdx.x;
    int start = g_off[n];
    int deg = g_off[n + 1] - start;
    int tid = threadIdx.x;
    float dn = g_dinv[n];
    int degc = deg < CAP ? deg : CAP;
    for (int i = tid; i < degc; i += 256) {
        int s = g_csrc[start + i];
        s_src[i] = s;
        s_nrm[i] = g_dinv[s] * g_cw[start + i] * dn;
    }
    __syncthreads();

    const float* hcol = g_h1f + tid;
    float acc = 0.f;
    int i = 0;
    for (; i + 3 < degc; i += 4) {
        float x0 = hcol[(size_t)s_src[i]     * F1];
        float x1 = hcol[(size_t)s_src[i + 1] * F1];
        float x2 = hcol[(size_t)s_src[i + 2] * F1];
        float x3 = hcol[(size_t)s_src[i + 3] * F1];
        acc = fmaf(x0, s_nrm[i],     acc);
        acc = fmaf(x1, s_nrm[i + 1], acc);
        acc = fmaf(x2, s_nrm[i + 2], acc);
        acc = fmaf(x3, s_nrm[i + 3], acc);
    }
    for (; i < deg; i++) {
        int src; float nrm;
        if (i < CAP) { src = s_src[i]; nrm = s_nrm[i]; }
        else {
            src = g_csrc[start + i];
            nrm = g_dinv[src] * g_cw[start + i] * dn;
        }
        acc = fmaf(hcol[(size_t)src * F1], nrm, acc);
    }
    __nv_bfloat16 hi = __float2bfloat16(acc);
    __nv_bfloat16 lo = __float2bfloat16(acc - __bfloat162float(hi));
    size_t rb = (size_t)n * (3 * F1);
    g_Az1[rb + tid]          = hi;
    g_Az1[rb + F1 + tid]     = lo;
    g_Az1[rb + 2 * F1 + tid] = hi;
}

// ---------------------------------------------------------------------------
// GCN aggregation over a1 (512 cols): z2 = S@a1 -> split into g_Az2.
// 128 threads x float4/thread, fast path unrolled x2.
// ---------------------------------------------------------------------------
__global__ __launch_bounds__(128) void k_agg_f2() {
    __shared__ int   s_src[CAP];
    __shared__ float s_nrm[CAP];
    int n = blockIdx.x;
    int start = g_off[n];
    int deg = g_off[n + 1] - start;
    int tid = threadIdx.x;
    float dn = g_dinv[n];
    int degc = deg < CAP ? deg : CAP;
    for (int i = tid; i < degc; i += 128) {
        int s = g_csrc[start + i];
        s_src[i] = s;
        s_nrm[i] = g_dinv[s] * g_cw[start + i] * dn;
    }
    __syncthreads();

    const float4* acol = (const float4*)(g_a1f) + tid;   // a1f row stride = 128 float4
    float4 acc = make_float4(0.f, 0.f, 0.f, 0.f);
    int i = 0;
    for (; i + 1 < degc; i += 2) {
        float4 x0 = acol[(size_t)s_src[i]     * 128];
        float4 x1 = acol[(size_t)s_src[i + 1] * 128];
        float n0 = s_nrm[i], n1 = s_nrm[i + 1];
        acc.x = fmaf(x0.x, n0, acc.x); acc.y = fmaf(x0.y, n0, acc.y);
        acc.z = fmaf(x0.z, n0, acc.z); acc.w = fmaf(x0.w, n0, acc.w);
        acc.x = fmaf(x1.x, n1, acc.x); acc.y = fmaf(x1.y, n1, acc.y);
        acc.z = fmaf(x1.z, n1, acc.z); acc.w = fmaf(x1.w, n1, acc.w);
    }
    for (; i < deg; i++) {
        int src; float nrm;
        if (i < CAP) { src = s_src[i]; nrm = s_nrm[i]; }
        else {
            src = g_csrc[start + i];
            nrm = g_dinv[src] * g_cw[start + i] * dn;
        }
        float4 x = acol[(size_t)src * 128];
        acc.x = fmaf(x.x, nrm, acc.x); acc.y = fmaf(x.y, nrm, acc.y);
        acc.z = fmaf(x.z, nrm, acc.z); acc.w = fmaf(x.w, nrm, acc.w);
    }
    int j = tid * 4;
    __nv_bfloat162 loA, loB;
    __nv_bfloat162 hiA = bsplit_hi2(acc.x, acc.y, loA);
    __nv_bfloat162 hiB = bsplit_hi2(acc.z, acc.w, loB);
    size_t rb = (size_t)n * (3 * F2);
    *(__nv_bfloat162*)(g_Az2 + rb + j)              = hiA;
    *(__nv_bfloat162*)(g_Az2 + rb + j + 2)          = hiB;
    *(__nv_bfloat162*)(g_Az2 + rb + F2 + j)         = loA;
    *(__nv_bfloat162*)(g_Az2 + rb + F2 + j + 2)     = loB;
    *(__nv_bfloat162*)(g_Az2 + rb + 2 * F2 + j)     = hiA;
    *(__nv_bfloat162*)(g_Az2 + rb + 2 * F2 + j + 2) = hiB;
}

// ---------------------------------------------------------------------------
// MLP head
// ---------------------------------------------------------------------------
__global__ __launch_bounds__(256) void k_head(
    const float* __restrict__ Wf1, const float* __restrict__ bf1,
    const float* __restrict__ Wf2, const float* __restrict__ bf2,
    float* __restrict__ out)
{
    __shared__ float sp[F3];
    __shared__ float sr0[256];
    __shared__ float sr1[256];
    int gb = blockIdx.x, tid = threadIdx.x;
    for (int i = tid; i < F3; i += 256) sp[i] = g_pool[(size_t)gb * F3 + i];
    __syncthreads();

    float acc = bf1[tid];
    #pragma unroll 4
    for (int k = 0; k < F3; ++k)
        acc = fmaf(sp[k], Wf1[(size_t)k * 256 + tid], acc);
    acc = acc > 0.f ? acc : 0.f;

    sr0[tid] = acc * Wf2[tid * 2 + 0];
    sr1[tid] = acc * Wf2[tid * 2 + 1];
    __syncthreads();
    for (int s = 128; s > 0; s >>= 1) {
        if (tid < s) { sr0[tid] += sr0[tid + s]; sr1[tid] += sr1[tid + s]; }
        __syncthreads();
    }
    if (tid == 0) {
        out[gb * 2 + 0] = sr0[0] + bf2[0];
        out[gb * 2 + 1] = sr1[0] + bf2[1];
    }
}

// ---------------------------------------------------------------------------
// Launch — two streams, event fork/join
// ---------------------------------------------------------------------------
extern "C" void kernel_launch(void* const* d_in, const int* in_sizes, int n_in,
                              void* d_out, int out_size)
{
    const float* x       = (const float*)d_in[0];
    const int*   ei      = (const int*)  d_in[1];
    const float* ew      = (const float*)d_in[2];
    const int*   batch   = (const int*)  d_in[3];
    const float* W_gat   = (const float*)d_in[4];
    const float* att_src = (const float*)d_in[5];
    const float* att_dst = (const float*)d_in[6];
    const float* b_gat   = (const float*)d_in[7];
    const float* W_res   = (const float*)d_in[8];
    const float* b_res   = (const float*)d_in[9];
    const float* W2      = (const float*)d_in[10];
    const float* b2      = (const float*)d_in[11];
    const float* g1      = (const float*)d_in[12];
    const float* be1     = (const float*)d_in[13];
    const float* m1      = (const float*)d_in[14];
    const float* v1      = (const float*)d_in[15];
    const float* W3      = (const float*)d_in[16];
    const float* b3      = (const float*)d_in[17];
    const float* g2      = (const float*)d_in[18];
    const float* be2     = (const float*)d_in[19];
    const float* m2      = (const float*)d_in[20];
    const float* v2      = (const float*)d_in[21];
    const float* Wf1     = (const float*)d_in[22];
    const float* bf1     = (const float*)d_in[23];
    const float* Wf2     = (const float*)d_in[24];
    const float* bf2     = (const float*)d_in[25];
    float* out = (float*)d_out;

    float *p_h0, *p_res, *p_a1f, *p_pool;
    __nv_bfloat16 *p_Ax, *p_Ab, *p_Az1, *p_Az2, *p_Bg, *p_Br, *p_B2, *p_B3;
    cudaGetSymbolAddress((void**)&p_h0,   g_h0);
    cudaGetSymbolAddress((void**)&p_res,  g_res);
    cudaGetSymbolAddress((void**)&p_a1f,  g_a1f);
    cudaGetSymbolAddress((void**)&p_pool, g_pool);
    cudaGetSymbolAddress((void**)&p_Ax,   g_Ax);
    cudaGetSymbolAddress((void**)&p_Ab,   g_Ab);
    cudaGetSymbolAddress((void**)&p_Az1,  g_Az1);
    cudaGetSymbolAddress((void**)&p_Az2,  g_Az2);
    cudaGetSymbolAddress((void**)&p_Bg,   g_Bg);
    cudaGetSymbolAddress((void**)&p_Br,   g_Br);
    cudaGetSymbolAddress((void**)&p_B2,   g_B2);
    cudaGetSymbolAddress((void**)&p_B3,   g_B3);

    cudaFuncSetAttribute(gemm_k<0>, cudaFuncAttributeMaxDynamicSharedMemorySize, GSM);
    cudaFuncSetAttribute(gemm_k<1>, cudaFuncAttributeMaxDynamicSharedMemorySize, GSM);
    cudaFuncSetAttribute(gemm_k<2>, cudaFuncAttributeMaxDynamicSharedMemorySize, GSM);

    const int rowTiles = (NN + 127) / 128;  // 157
    const int egrid = (EPQ + 255) / 256;

    // ---- fork: side stream does CSR build + weight splits -----------------
    cudaEventRecord(g_ev_start, 0);
    cudaStreamWaitEvent(g_s2, g_ev_start, 0);

    k_init <<<512,   256, 0, g_s2>>>();
    k_count<<<egrid, 256, 0, g_s2>>>(ei, ew);
    k_scan <<<1,    1024, 0, g_s2>>>();
    k_fill <<<egrid, 256, 0, g_s2>>>(ei, ew);
    k_splitB<<<1024, 256, 0, g_s2>>>(W_res, p_Br, F1, F3);
    k_splitB<<<512,  256, 0, g_s2>>>(W2,    p_B2, F1, F2);
    k_splitB<<<2048, 256, 0, g_s2>>>(W3,    p_B3, F2, F3);
    cudaEventRecord(g_ev_csr, g_s2);

    // ---- main: GAT GEMM chain (concurrent with side) ----------------------
    k_splitA<<<2048, 256>>>(x, p_Ax, NN, 32);
    k_splitB<<<64,   256>>>(W_gat, p_Bg, 32, F1);
    gemm_k<0><<<dim3(F1 / 128, rowTiles), 256, GSM>>>(
        p_Ax, p_Bg, p_h0, nullptr, nullptr, nullptr, nullptr, nullptr,
        nullptr, nullptr, nullptr, NN, F1, 96);
    k_attn_dots<<<(NN * HHH + 255) / 256, 256>>>(att_src, att_dst);

    cudaStreamWaitEvent(0, g_ev_csr, 0);            // join: need CSR
    k_gat_gather<<<NN, 256>>>(b_gat);               // h1 fp32 + split in g_Ab
    cudaEventRecord(g_ev_h1, 0);

    // ---- fork 2: residual GEMM on side, GCN chain on main -----------------
    cudaStreamWaitEvent(g_s2, g_ev_h1, 0);
    gemm_k<0><<<dim3(F3 / 128, rowTiles), 256, GSM, g_s2>>>(
        p_Ab, p_Br, p_res, b_res, nullptr, nullptr, nullptr, nullptr,
        nullptr, nullptr, nullptr, NN, F3, 768);
    cudaEventRecord(g_ev_res, g_s2);

    k_agg_f1<<<NN, 256>>>();                        // z1 split -> g_Az1
    gemm_k<1><<<dim3(F2 / 128, rowTiles), 256, GSM>>>(
        p_Az1, p_B2, p_a1f, b2, g1, be1, m1, v1,
        nullptr, nullptr, nullptr, NN, F2, 768);
    k_agg_f2<<<NN, 128>>>();                        // z2 split -> g_Az2

    cudaStreamWaitEvent(0, g_ev_res, 0);            // join: need g_res
    gemm_k<2><<<dim3(F3 / 128, rowTiles), 256, GSM>>>(
        p_Az2, p_B3, nullptr, b3, g2, be2, m2, v2,
        p_res, batch, p_pool, NN, F3, 1536);

    // MLP head
    k_head<<<GGG, 256>>>(Wf1, bf1, Wf2, bf2, out);
}